// round 2
// baseline (speedup 1.0000x reference)
#include <cuda_runtime.h>
#include <cmath>

#define BB 2
#define LL 2048
#define DD 2048
#define HH 16
#define DH 128

// ---------------- scratch (static device arrays; no allocation allowed) ----------------
__device__ float g_q[(size_t)BB * HH * LL * DH];
__device__ float g_k[(size_t)BB * HH * LL * DH];
__device__ float g_v[(size_t)BB * HH * LL * DH];
__device__ float g_attn[(size_t)BB * LL * DD];
__device__ float g_invf[64];

// ---------------- inv_freqs in fp64 once (64 values, trivial) ----------------
__global__ void build_invf_kernel() {
    int i = threadIdx.x;
    if (i < 64) {
        double e = (double)(2 * i) / 128.0;
        g_invf[i] = (float)pow(500000.0, -e);
    }
}

// ---------------- fp32 SGEMM: C[M,N] = A[M,K] @ B[K,N], 128x128x8, 8x8/thread ----------------
// SCATTER=1: C is written as [b][h][l][dh] (for q/k/v), else plain row-major.
template <int SCATTER>
__global__ __launch_bounds__(256)
void sgemm_kernel(const float* __restrict__ A, const float* __restrict__ Bm,
                  float* __restrict__ C, int M, int N, int K)
{
    __shared__ __align__(16) float As[8][128];
    __shared__ __align__(16) float Bs[8][128];
    const int tid = threadIdx.x;
    const int tx = tid & 15, ty = tid >> 4;
    const int bx = blockIdx.x, by = blockIdx.y;
    const int a_row = tid >> 1, a_col = (tid & 1) * 4;
    const int b_row = tid >> 5, b_col = (tid & 31) * 4;
    const float* Ab = A + (size_t)(by * 128 + a_row) * K + a_col;
    const float* Bb = Bm + (size_t)b_row * N + bx * 128 + b_col;

    float acc[8][8];
#pragma unroll
    for (int i = 0; i < 8; i++)
#pragma unroll
        for (int j = 0; j < 8; j++) acc[i][j] = 0.f;

    for (int kt = 0; kt < K; kt += 8) {
        float4 av = *(const float4*)(Ab + kt);
        float4 bv = *(const float4*)(Bb + (size_t)kt * N);
        As[a_col + 0][a_row] = av.x;
        As[a_col + 1][a_row] = av.y;
        As[a_col + 2][a_row] = av.z;
        As[a_col + 3][a_row] = av.w;
        *(float4*)&Bs[b_row][b_col] = bv;
        __syncthreads();
#pragma unroll
        for (int kk = 0; kk < 8; kk++) {
            float a[8], b[8];
            *(float4*)(a)     = *(const float4*)&As[kk][ty * 8];
            *(float4*)(a + 4) = *(const float4*)&As[kk][ty * 8 + 4];
            *(float4*)(b)     = *(const float4*)&Bs[kk][tx * 8];
            *(float4*)(b + 4) = *(const float4*)&Bs[kk][tx * 8 + 4];
#pragma unroll
            for (int i = 0; i < 8; i++)
#pragma unroll
                for (int j = 0; j < 8; j++)
                    acc[i][j] = fmaf(a[i], b[j], acc[i][j]);
        }
        __syncthreads();
    }

#pragma unroll
    for (int i = 0; i < 8; i++) {
        const int row = by * 128 + ty * 8 + i;
#pragma unroll
        for (int j = 0; j < 8; j++) {
            const int col = bx * 128 + tx * 8 + j;
            if (SCATTER) {
                const int b_ = row / LL, lpos = row % LL;
                const int h = col >> 7, dh = col & 127;
                C[(((size_t)(b_ * HH + h)) * LL + lpos) * DH + dh] = acc[i][j];
            } else {
                C[(size_t)row * N + col] = acc[i][j];
            }
        }
    }
}

// ---------------- RoPE + L2-normalize (one warp per (b,h,l) row of 128) ----------------
__global__ __launch_bounds__(256)
void rope_norm_kernel(float* __restrict__ t)
{
    const int gw = (blockIdx.x * 256 + threadIdx.x) >> 5;  // row id, exact grid
    const int lane = threadIdx.x & 31;
    const int pos = gw & (LL - 1);
    float* row = t + (size_t)gw * DH;

    const float invf0 = g_invf[lane];
    const float invf1 = g_invf[lane + 32];
    const float pf = (float)pos;
    float s0, c0, s1, c1;
    sincosf(pf * invf0, &s0, &c0);
    sincosf(pf * invf1, &s1, &c1);

    float2 x = ((const float2*)row)[lane];
    float2 y = ((const float2*)row)[lane + 32];
    const float r0 = x.x * c0 - x.y * s0;
    const float r1 = x.y * c0 + x.x * s0;
    const float r2 = y.x * c1 - y.y * s1;
    const float r3 = y.y * c1 + y.x * s1;

    float ss = r0 * r0 + r1 * r1 + r2 * r2 + r3 * r3;
#pragma unroll
    for (int off = 16; off > 0; off >>= 1)
        ss += __shfl_xor_sync(0xffffffffu, ss, off);
    const float inv = 1.0f / (sqrtf(ss) + 1e-6f);

    ((float2*)row)[lane]      = make_float2(r0 * inv, r1 * inv);
    ((float2*)row)[lane + 32] = make_float2(r2 * inv, r3 * inv);
}

// ---------------- causal flash attention, fp32, 64q x 64k tiles ----------------
// smem: q_s[128][64] (d-major), k_s[128][64], v_s[64][128], p_s[64][65]
#define ATTN_SMEM_FLOATS (8192 + 8192 + 8192 + 64 * 65)
#define ATTN_SMEM_BYTES (ATTN_SMEM_FLOATS * 4)

__global__ __launch_bounds__(256, 1)
void attn_kernel(const float* __restrict__ scale_ptr)
{
    extern __shared__ __align__(16) float sm[];
    float* q_s = sm;             // [128][64]
    float* k_s = sm + 8192;      // [128][64]
    float* v_s = sm + 16384;     // [64][128]
    float* p_s = sm + 24576;     // [64][65] (padded)

    const int qt = blockIdx.x;
    const int h  = blockIdx.y;
    const int b  = blockIdx.z;
    const int tid = threadIdx.x;
    const int tx = tid & 15, ty = tid >> 4;
    const float scale = *scale_ptr;

    const size_t head_off = (size_t)(b * HH + h) * LL * DH;
    const float* qptr = g_q + head_off;
    const float* kptr = g_k + head_off;
    const float* vptr = g_v + head_off;
    const int q0 = qt * 64;

    // load Q tile transposed (d-major)
    {
        const int r = tid >> 2;
        const int d0 = (tid & 3) * 32;
        const float* src = qptr + (size_t)(q0 + r) * DH + d0;
#pragma unroll
        for (int j = 0; j < 32; j += 4) {
            float4 t4 = *(const float4*)(src + j);
            q_s[(d0 + j + 0) * 64 + r] = t4.x;
            q_s[(d0 + j + 1) * 64 + r] = t4.y;
            q_s[(d0 + j + 2) * 64 + r] = t4.z;
            q_s[(d0 + j + 3) * 64 + r] = t4.w;
        }
    }

    float m[4], l[4], o[4][8];
#pragma unroll
    for (int i = 0; i < 4; i++) {
        m[i] = -INFINITY;
        l[i] = 0.f;
#pragma unroll
        for (int j = 0; j < 8; j++) o[i][j] = 0.f;
    }

    for (int kt = 0; kt <= qt; kt++) {
        const int k0 = kt * 64;
        __syncthreads();  // protect k_s/v_s/p_s from prior-iteration readers
        {
            const int r = tid >> 2;
            const int d0 = (tid & 3) * 32;
            const float* src = kptr + (size_t)(k0 + r) * DH + d0;
#pragma unroll
            for (int j = 0; j < 32; j += 4) {
                float4 t4 = *(const float4*)(src + j);
                k_s[(d0 + j + 0) * 64 + r] = t4.x;
                k_s[(d0 + j + 1) * 64 + r] = t4.y;
                k_s[(d0 + j + 2) * 64 + r] = t4.z;
                k_s[(d0 + j + 3) * 64 + r] = t4.w;
            }
            const float4* vsrc = (const float4*)(vptr + (size_t)k0 * DH);
            float4* vdst = (float4*)v_s;
#pragma unroll
            for (int i2 = 0; i2 < 8; i2++)
                vdst[tid + i2 * 256] = vsrc[tid + i2 * 256];
        }
        __syncthreads();

        // S = Q K^T  (64x64, K=128)
        float s[4][4];
#pragma unroll
        for (int i = 0; i < 4; i++)
#pragma unroll
            for (int j = 0; j < 4; j++) s[i][j] = 0.f;

#pragma unroll 8
        for (int d = 0; d < 128; d++) {
            float4 aq = *(const float4*)(q_s + d * 64 + ty * 4);
            float4 bk = *(const float4*)(k_s + d * 64 + tx * 4);
            float av[4] = {aq.x, aq.y, aq.z, aq.w};
            float bv[4] = {bk.x, bk.y, bk.z, bk.w};
#pragma unroll
            for (int i = 0; i < 4; i++)
#pragma unroll
                for (int j = 0; j < 4; j++)
                    s[i][j] = fmaf(av[i], bv[j], s[i][j]);
        }

        // mask + scale + online softmax
#pragma unroll
        for (int i = 0; i < 4; i++) {
            const int qrow = q0 + ty * 4 + i;
            float rmax = -INFINITY;
#pragma unroll
            for (int j = 0; j < 4; j++) {
                const float val = (k0 + tx * 4 + j <= qrow) ? s[i][j] * scale : -INFINITY;
                s[i][j] = val;
                rmax = fmaxf(rmax, val);
            }
#pragma unroll
            for (int off = 8; off > 0; off >>= 1)
                rmax = fmaxf(rmax, __shfl_xor_sync(0xffffffffu, rmax, off, 16));
            const float mn = fmaxf(m[i], rmax);
            const float f = expf(m[i] - mn);
            float rs = 0.f;
#pragma unroll
            for (int j = 0; j < 4; j++) {
                const float pv = expf(s[i][j] - mn);
                s[i][j] = pv;
                rs += pv;
            }
#pragma unroll
            for (int off = 8; off > 0; off >>= 1)
                rs += __shfl_xor_sync(0xffffffffu, rs, off, 16);
            l[i] = l[i] * f + rs;
            m[i] = mn;
#pragma unroll
            for (int j = 0; j < 8; j++) o[i][j] *= f;
#pragma unroll
            for (int j = 0; j < 4; j++)
                p_s[(tx * 4 + j) * 65 + ty * 4 + i] = s[i][j];
        }
        __syncthreads();

        // O += P @ V   (64x128, K=64)
#pragma unroll 4
        for (int kk = 0; kk < 64; kk++) {
            float aa[4];
            aa[0] = p_s[kk * 65 + ty * 4 + 0];
            aa[1] = p_s[kk * 65 + ty * 4 + 1];
            aa[2] = p_s[kk * 65 + ty * 4 + 2];
            aa[3] = p_s[kk * 65 + ty * 4 + 3];
            float4 b0 = *(const float4*)(v_s + kk * 128 + tx * 8);
            float4 b1 = *(const float4*)(v_s + kk * 128 + tx * 8 + 4);
            float bb[8] = {b0.x, b0.y, b0.z, b0.w, b1.x, b1.y, b1.z, b1.w};
#pragma unroll
            for (int i = 0; i < 4; i++)
#pragma unroll
                for (int j = 0; j < 8; j++)
                    o[i][j] = fmaf(aa[i], bb[j], o[i][j]);
        }
    }

    // write normalized output, layout [b][l][h*Dh + dh]
#pragma unroll
    for (int i = 0; i < 4; i++) {
        const int qrow = q0 + ty * 4 + i;
        const float inv = 1.0f / l[i];
        float* dst = g_attn + ((size_t)(b * LL + qrow)) * DD + h * DH + tx * 8;
        float4 w0 = make_float4(o[i][0] * inv, o[i][1] * inv, o[i][2] * inv, o[i][3] * inv);
        float4 w1 = make_float4(o[i][4] * inv, o[i][5] * inv, o[i][6] * inv, o[i][7] * inv);
        *(float4*)(dst)     = w0;
        *(float4*)(dst + 4) = w1;
    }
}

// ---------------- launch ----------------
extern "C" void kernel_launch(void* const* d_in, const int* in_sizes, int n_in,
                              void* d_out, int out_size)
{
    const float* x     = (const float*)d_in[0];
    const float* Wq    = (const float*)d_in[1];
    const float* Wk    = (const float*)d_in[2];
    const float* Wv    = (const float*)d_in[3];
    const float* Wout  = (const float*)d_in[4];
    const float* scale = (const float*)d_in[5];
    float* out = (float*)d_out;

    float *qp, *kp, *vp, *ap;
    cudaGetSymbolAddress((void**)&qp, g_q);
    cudaGetSymbolAddress((void**)&kp, g_k);
    cudaGetSymbolAddress((void**)&vp, g_v);
    cudaGetSymbolAddress((void**)&ap, g_attn);

    build_invf_kernel<<<1, 64>>>();

    const int M = BB * LL;  // 4096
    dim3 gemm_grid(DD / 128, M / 128);

    sgemm_kernel<1><<<gemm_grid, 256>>>(x, Wq, qp, M, DD, DD);
    sgemm_kernel<1><<<gemm_grid, 256>>>(x, Wk, kp, M, DD, DD);
    sgemm_kernel<1><<<gemm_grid, 256>>>(x, Wv, vp, M, DD, DD);

    const int rope_blocks = (BB * HH * LL) / 8;  // 8 warps/block
    rope_norm_kernel<<<rope_blocks, 256>>>(qp);
    rope_norm_kernel<<<rope_blocks, 256>>>(kp);

    cudaFuncSetAttribute(attn_kernel, cudaFuncAttributeMaxDynamicSharedMemorySize,
                         ATTN_SMEM_BYTES);
    attn_kernel<<<dim3(LL / 64, HH, BB), 256, ATTN_SMEM_BYTES>>>(scale);

    sgemm_kernel<0><<<gemm_grid, 256>>>(ap, Wout, out, M, DD, DD);
}

// round 6
// speedup vs baseline: 2.2095x; 2.2095x over previous
#include <cuda_runtime.h>
#include <cstdint>
#include <cmath>

#define BB 2
#define LL 2048
#define DD 2048
#define HH 16
#define DH 128

// ---------------- scratch ----------------
__device__ float g_q[(size_t)BB * HH * LL * DH];
__device__ float g_k[(size_t)BB * HH * LL * DH];
__device__ float g_v[(size_t)BB * HH * LL * DH];
__device__ float g_attn[(size_t)BB * LL * DD];
__device__ float g_invf[64];

__global__ void build_invf_kernel() {
    int i = threadIdx.x;
    if (i < 64) {
        double e = (double)(2 * i) / 128.0;
        g_invf[i] = (float)pow(500000.0, -e);
    }
}

// ============================================================================
// tf32 mma.sync GEMM: C[M,N] = A[M,K] @ B[K,N]  (fp32 in/out, tf32 HMMA)
// CTA tile 128x128, K-tile 32, 8 warps (2m x 4n), warp tile 64x32.
// Double-buffered SMEM via cp.async.
// ============================================================================

__device__ __forceinline__ uint32_t smem_u32(const void* p) {
    uint32_t a;
    asm("{ .reg .u64 t; cvta.to.shared.u64 t, %1; cvt.u32.u64 %0, t; }"
        : "=r"(a) : "l"(p));
    return a;
}

__device__ __forceinline__ uint32_t f2tf32(float f) {
    uint32_t u;
    asm("cvt.rna.tf32.f32 %0, %1;" : "=r"(u) : "f"(f));
    return u;
}

#define CP_ASYNC16(saddr, gptr)                                               \
    asm volatile("cp.async.cg.shared.global [%0], [%1], 16;"                  \
                 :: "r"(saddr), "l"(gptr))
#define CP_COMMIT() asm volatile("cp.async.commit_group;")
#define CP_WAIT(n)  asm volatile("cp.async.wait_group %0;" :: "n"(n))

#define ASTRIDE 36              // floats
#define BSTRIDE 136             // floats
#define A_FLOATS (128 * ASTRIDE)       // 4608
#define B_FLOATS (32 * BSTRIDE)        // 4352
#define BUF_FLOATS (A_FLOATS + B_FLOATS)  // 8960
#define GEMM_SMEM_BYTES (2 * BUF_FLOATS * 4)  // 71680

template <int SCATTER>
__global__ __launch_bounds__(256, 2)
void mma_gemm_kernel(const float* __restrict__ A, const float* __restrict__ Bm,
                     float* __restrict__ C, int M, int N, int K)
{
    extern __shared__ __align__(16) float sm[];
    const int tid = threadIdx.x;
    const int wid = tid >> 5;
    const int lane = tid & 31;
    const int warp_m = wid >> 2;       // 0..1
    const int warp_n = wid & 3;        // 0..3
    const int bx = blockIdx.x, by = blockIdx.y;
    const int m0 = by * 128, n0 = bx * 128;
    const uint32_t sbase = smem_u32(sm);

    // per-thread load slots
    const int a_m  = tid >> 3,  a_kq = tid & 7;     // +32 rows per i
    const int b_k  = tid >> 5,  b_nq = tid & 31;    // +8 k-rows per i

    const float* aG0 = A + (size_t)(m0 + a_m) * K + a_kq * 4;
    const float* bG0 = Bm + (size_t)b_k * N + n0 + b_nq * 4;
    const uint32_t aS0 = sbase + (uint32_t)(a_m * ASTRIDE + a_kq * 4) * 4;
    const uint32_t bS0 = sbase + (uint32_t)(A_FLOATS + b_k * BSTRIDE + b_nq * 4) * 4;

#define LOAD_TILE(kt, buf) do {                                               \
    const uint32_t off = (uint32_t)(buf) * (BUF_FLOATS * 4);                  \
    _Pragma("unroll")                                                         \
    for (int i = 0; i < 4; i++)                                               \
        CP_ASYNC16(aS0 + off + (uint32_t)(i * 32 * ASTRIDE) * 4,              \
                   aG0 + (size_t)(i * 32) * K + (kt) * 32);                   \
    _Pragma("unroll")                                                         \
    for (int i = 0; i < 4; i++)                                               \
        CP_ASYNC16(bS0 + off + (uint32_t)(i * 8 * BSTRIDE) * 4,               \
                   bG0 + (size_t)((kt) * 32 + i * 8) * N);                    \
    CP_COMMIT();                                                              \
} while (0)

    float acc[4][4][4];
#pragma unroll
    for (int mt = 0; mt < 4; mt++)
#pragma unroll
        for (int nt = 0; nt < 4; nt++)
#pragma unroll
            for (int r = 0; r < 4; r++) acc[mt][nt][r] = 0.f;

    const int KT = K / 32;
    LOAD_TILE(0, 0);

    const int fr_row = lane >> 2;     // 0..7
    const int fr_col = lane & 3;      // 0..3

    for (int kt = 0; kt < KT; kt++) {
        const int buf = kt & 1;
        if (kt + 1 < KT) {
            LOAD_TILE(kt + 1, (kt + 1) & 1);
            CP_WAIT(1);
        } else {
            CP_WAIT(0);
        }
        __syncthreads();

        const float* As = sm + buf * BUF_FLOATS;
        const float* Bs = As + A_FLOATS;

#pragma unroll
        for (int s = 0; s < 4; s++) {
            const int kb = s * 8;
            uint32_t af[4][4], bf[4][2];
#pragma unroll
            for (int mt = 0; mt < 4; mt++) {
                const float* ap = As + (warp_m * 64 + mt * 16 + fr_row) * ASTRIDE + kb + fr_col;
                af[mt][0] = f2tf32(ap[0]);
                af[mt][1] = f2tf32(ap[8 * ASTRIDE]);
                af[mt][2] = f2tf32(ap[4]);
                af[mt][3] = f2tf32(ap[8 * ASTRIDE + 4]);
            }
#pragma unroll
            for (int nt = 0; nt < 4; nt++) {
                const float* bp = Bs + (kb + fr_col) * BSTRIDE + warp_n * 32 + nt * 8 + fr_row;
                bf[nt][0] = f2tf32(bp[0]);
                bf[nt][1] = f2tf32(bp[4 * BSTRIDE]);
            }
#pragma unroll
            for (int mt = 0; mt < 4; mt++)
#pragma unroll
                for (int nt = 0; nt < 4; nt++) {
                    asm volatile(
                        "mma.sync.aligned.m16n8k8.row.col.f32.tf32.tf32.f32 "
                        "{%0,%1,%2,%3}, {%4,%5,%6,%7}, {%8,%9}, {%0,%1,%2,%3};"
                        : "+f"(acc[mt][nt][0]), "+f"(acc[mt][nt][1]),
                          "+f"(acc[mt][nt][2]), "+f"(acc[mt][nt][3])
                        : "r"(af[mt][0]), "r"(af[mt][1]), "r"(af[mt][2]), "r"(af[mt][3]),
                          "r"(bf[nt][0]), "r"(bf[nt][1]));
                }
        }
        __syncthreads();
    }

    // epilogue
#pragma unroll
    for (int mt = 0; mt < 4; mt++) {
#pragma unroll
        for (int nt = 0; nt < 4; nt++) {
            const int r0 = m0 + warp_m * 64 + mt * 16 + fr_row;
            const int nloc = warp_n * 32 + nt * 8 + fr_col * 2;
            float2 v0 = make_float2(acc[mt][nt][0], acc[mt][nt][1]);
            float2 v1 = make_float2(acc[mt][nt][2], acc[mt][nt][3]);
            if (SCATTER) {
                const int b0_ = r0 >> 11, l0 = r0 & 2047;
                const int b1_ = (r0 + 8) >> 11, l1 = (r0 + 8) & 2047;
                *(float2*)(C + (((size_t)(b0_ * HH + bx)) * LL + l0) * DH + nloc) = v0;
                *(float2*)(C + (((size_t)(b1_ * HH + bx)) * LL + l1) * DH + nloc) = v1;
            } else {
                *(float2*)(C + (size_t)r0 * N + n0 + nloc) = v0;
                *(float2*)(C + (size_t)(r0 + 8) * N + n0 + nloc) = v1;
            }
        }
    }
#undef LOAD_TILE
}

// ---------------- RoPE + L2-normalize ----------------
__global__ __launch_bounds__(256)
void rope_norm_kernel(float* __restrict__ t)
{
    const int gw = (blockIdx.x * 256 + threadIdx.x) >> 5;
    const int lane = threadIdx.x & 31;
    const int pos = gw & (LL - 1);
    float* row = t + (size_t)gw * DH;

    const float invf0 = g_invf[lane];
    const float invf1 = g_invf[lane + 32];
    const float pf = (float)pos;
    float s0, c0, s1, c1;
    sincosf(pf * invf0, &s0, &c0);
    sincosf(pf * invf1, &s1, &c1);

    float2 x = ((const float2*)row)[lane];
    float2 y = ((const float2*)row)[lane + 32];
    const float r0 = x.x * c0 - x.y * s0;
    const float r1 = x.y * c0 + x.x * s0;
    const float r2 = y.x * c1 - y.y * s1;
    const float r3 = y.y * c1 + y.x * s1;

    float ss = r0 * r0 + r1 * r1 + r2 * r2 + r3 * r3;
#pragma unroll
    for (int off = 16; off > 0; off >>= 1)
        ss += __shfl_xor_sync(0xffffffffu, ss, off);
    const float inv = 1.0f / (sqrtf(ss) + 1e-6f);

    ((float2*)row)[lane]      = make_float2(r0 * inv, r1 * inv);
    ((float2*)row)[lane + 32] = make_float2(r2 * inv, r3 * inv);
}

// ---------------- causal flash attention, fp32, 64q x 64k tiles ----------------
#define ATTN_SMEM_FLOATS (8192 + 8192 + 8192 + 64 * 65)
#define ATTN_SMEM_BYTES (ATTN_SMEM_FLOATS * 4)

__global__ __launch_bounds__(256, 1)
void attn_kernel(const float* __restrict__ scale_ptr)
{
    extern __shared__ __align__(16) float sm[];
    float* q_s = sm;             // [128][64]
    float* k_s = sm + 8192;      // [128][64]
    float* v_s = sm + 16384;     // [64][128]
    float* p_s = sm + 24576;     // [64][65]

    const int qt = blockIdx.x;
    const int h  = blockIdx.y;
    const int b  = blockIdx.z;
    const int tid = threadIdx.x;
    const int tx = tid & 15, ty = tid >> 4;
    const float scale = *scale_ptr;

    const size_t head_off = (size_t)(b * HH + h) * LL * DH;
    const float* qptr = g_q + head_off;
    const float* kptr = g_k + head_off;
    const float* vptr = g_v + head_off;
    const int q0 = qt * 64;

    {
        const int r = tid >> 2;
        const int d0 = (tid & 3) * 32;
        const float* src = qptr + (size_t)(q0 + r) * DH + d0;
#pragma unroll
        for (int j = 0; j < 32; j += 4) {
            float4 t4 = *(const float4*)(src + j);
            q_s[(d0 + j + 0) * 64 + r] = t4.x;
            q_s[(d0 + j + 1) * 64 + r] = t4.y;
            q_s[(d0 + j + 2) * 64 + r] = t4.z;
            q_s[(d0 + j + 3) * 64 + r] = t4.w;
        }
    }

    float m[4], l[4], o[4][8];
#pragma unroll
    for (int i = 0; i < 4; i++) {
        m[i] = -INFINITY;
        l[i] = 0.f;
#pragma unroll
        for (int j = 0; j < 8; j++) o[i][j] = 0.f;
    }

    for (int kt = 0; kt <= qt; kt++) {
        const int k0 = kt * 64;
        __syncthreads();
        {
            const int r = tid >> 2;
            const int d0 = (tid & 3) * 32;
            const float* src = kptr + (size_t)(k0 + r) * DH + d0;
#pragma unroll
            for (int j = 0; j < 32; j += 4) {
                float4 t4 = *(const float4*)(src + j);
                k_s[(d0 + j + 0) * 64 + r] = t4.x;
                k_s[(d0 + j + 1) * 64 + r] = t4.y;
                k_s[(d0 + j + 2) * 64 + r] = t4.z;
                k_s[(d0 + j + 3) * 64 + r] = t4.w;
            }
            const float4* vsrc = (const float4*)(vptr + (size_t)k0 * DH);
            float4* vdst = (float4*)v_s;
#pragma unroll
            for (int i2 = 0; i2 < 8; i2++)
                vdst[tid + i2 * 256] = vsrc[tid + i2 * 256];
        }
        __syncthreads();

        float s[4][4];
#pragma unroll
        for (int i = 0; i < 4; i++)
#pragma unroll
            for (int j = 0; j < 4; j++) s[i][j] = 0.f;

#pragma unroll 8
        for (int d = 0; d < 128; d++) {
            float4 aq = *(const float4*)(q_s + d * 64 + ty * 4);
            float4 bk = *(const float4*)(k_s + d * 64 + tx * 4);
            float av[4] = {aq.x, aq.y, aq.z, aq.w};
            float bv[4] = {bk.x, bk.y, bk.z, bk.w};
#pragma unroll
            for (int i = 0; i < 4; i++)
#pragma unroll
                for (int j = 0; j < 4; j++)
                    s[i][j] = fmaf(av[i], bv[j], s[i][j]);
        }

#pragma unroll
        for (int i = 0; i < 4; i++) {
            const int qrow = q0 + ty * 4 + i;
            float rmax = -INFINITY;
#pragma unroll
            for (int j = 0; j < 4; j++) {
                const float val = (k0 + tx * 4 + j <= qrow) ? s[i][j] * scale : -INFINITY;
                s[i][j] = val;
                rmax = fmaxf(rmax, val);
            }
#pragma unroll
            for (int off = 8; off > 0; off >>= 1)
                rmax = fmaxf(rmax, __shfl_xor_sync(0xffffffffu, rmax, off, 16));
            const float mn = fmaxf(m[i], rmax);
            const float f = expf(m[i] - mn);
            float rs = 0.f;
#pragma unroll
            for (int j = 0; j < 4; j++) {
                const float pv = expf(s[i][j] - mn);
                s[i][j] = pv;
                rs += pv;
            }
#pragma unroll
            for (int off = 8; off > 0; off >>= 1)
                rs += __shfl_xor_sync(0xffffffffu, rs, off, 16);
            l[i] = l[i] * f + rs;
            m[i] = mn;
#pragma unroll
            for (int j = 0; j < 8; j++) o[i][j] *= f;
#pragma unroll
            for (int j = 0; j < 4; j++)
                p_s[(tx * 4 + j) * 65 + ty * 4 + i] = s[i][j];
        }
        __syncthreads();

#pragma unroll 4
        for (int kk = 0; kk < 64; kk++) {
            float aa[4];
            aa[0] = p_s[kk * 65 + ty * 4 + 0];
            aa[1] = p_s[kk * 65 + ty * 4 + 1];
            aa[2] = p_s[kk * 65 + ty * 4 + 2];
            aa[3] = p_s[kk * 65 + ty * 4 + 3];
            float4 b0 = *(const float4*)(v_s + kk * 128 + tx * 8);
            float4 b1 = *(const float4*)(v_s + kk * 128 + tx * 8 + 4);
            float bb[8] = {b0.x, b0.y, b0.z, b0.w, b1.x, b1.y, b1.z, b1.w};
#pragma unroll
            for (int i = 0; i < 4; i++)
#pragma unroll
                for (int j = 0; j < 8; j++)
                    o[i][j] = fmaf(aa[i], bb[j], o[i][j]);
        }
    }

#pragma unroll
    for (int i = 0; i < 4; i++) {
        const int qrow = q0 + ty * 4 + i;
        const float inv = 1.0f / l[i];
        float* dst = g_attn + ((size_t)(b * LL + qrow)) * DD + h * DH + tx * 8;
        float4 w0 = make_float4(o[i][0] * inv, o[i][1] * inv, o[i][2] * inv, o[i][3] * inv);
        float4 w1 = make_float4(o[i][4] * inv, o[i][5] * inv, o[i][6] * inv, o[i][7] * inv);
        *(float4*)(dst)     = w0;
        *(float4*)(dst + 4) = w1;
    }
}

// ---------------- launch ----------------
extern "C" void kernel_launch(void* const* d_in, const int* in_sizes, int n_in,
                              void* d_out, int out_size)
{
    const float* x     = (const float*)d_in[0];
    const float* Wq    = (const float*)d_in[1];
    const float* Wk    = (const float*)d_in[2];
    const float* Wv    = (const float*)d_in[3];
    const float* Wout  = (const float*)d_in[4];
    const float* scale = (const float*)d_in[5];
    float* out = (float*)d_out;

    float *qp, *kp, *vp, *ap;
    cudaGetSymbolAddress((void**)&qp, g_q);
    cudaGetSymbolAddress((void**)&kp, g_k);
    cudaGetSymbolAddress((void**)&vp, g_v);
    cudaGetSymbolAddress((void**)&ap, g_attn);

    build_invf_kernel<<<1, 64>>>();

    const int M = BB * LL;  // 4096
    dim3 gemm_grid(DD / 128, M / 128);

    cudaFuncSetAttribute(mma_gemm_kernel<1>, cudaFuncAttributeMaxDynamicSharedMemorySize,
                         GEMM_SMEM_BYTES);
    cudaFuncSetAttribute(mma_gemm_kernel<0>, cudaFuncAttributeMaxDynamicSharedMemorySize,
                         GEMM_SMEM_BYTES);

    mma_gemm_kernel<1><<<gemm_grid, 256, GEMM_SMEM_BYTES>>>(x, Wq, qp, M, DD, DD);
    mma_gemm_kernel<1><<<gemm_grid, 256, GEMM_SMEM_BYTES>>>(x, Wk, kp, M, DD, DD);
    mma_gemm_kernel<1><<<gemm_grid, 256, GEMM_SMEM_BYTES>>>(x, Wv, vp, M, DD, DD);

    const int rope_blocks = (BB * HH * LL) / 8;
    rope_norm_kernel<<<rope_blocks, 256>>>(qp);
    rope_norm_kernel<<<rope_blocks, 256>>>(kp);

    cudaFuncSetAttribute(attn_kernel, cudaFuncAttributeMaxDynamicSharedMemorySize,
                         ATTN_SMEM_BYTES);
    attn_kernel<<<dim3(LL / 64, HH, BB), 256, ATTN_SMEM_BYTES>>>(scale);

    mma_gemm_kernel<0><<<gemm_grid, 256, GEMM_SMEM_BYTES>>>(ap, Wout, out, M, DD, DD);
}

// round 8
// speedup vs baseline: 3.2399x; 1.4664x over previous
#include <cuda_runtime.h>
#include <cstdint>
#include <cmath>

#define BB 2
#define LL 2048
#define DD 2048
#define HH 16
#define DH 128

// ---------------- scratch ----------------
__device__ float g_q[(size_t)BB * HH * LL * DH];
__device__ float g_k[(size_t)BB * HH * LL * DH];
__device__ float g_v[(size_t)BB * HH * LL * DH];
__device__ float g_attn[(size_t)BB * LL * DD];
__device__ float g_invf[64];

__global__ void build_invf_kernel() {
    int i = threadIdx.x;
    if (i < 64) {
        double e = (double)(2 * i) / 128.0;
        g_invf[i] = (float)pow(500000.0, -e);
    }
}

__device__ __forceinline__ uint32_t smem_u32(const void* p) {
    uint32_t a;
    asm("{ .reg .u64 t; cvta.to.shared.u64 t, %1; cvt.u32.u64 %0, t; }"
        : "=r"(a) : "l"(p));
    return a;
}

__device__ __forceinline__ uint32_t f2tf32(float f) {
    uint32_t u;
    asm("cvt.rna.tf32.f32 %0, %1;" : "=r"(u) : "f"(f));
    return u;
}

__device__ __forceinline__ float fast_exp2(float x) {
    float r;
    asm("ex2.approx.ftz.f32 %0, %1;" : "=f"(r) : "f"(x));
    return r;
}

#define MMA_TF32(acc, a0, a1, a2, a3, b0, b1)                                 \
    asm volatile(                                                             \
        "mma.sync.aligned.m16n8k8.row.col.f32.tf32.tf32.f32 "                 \
        "{%0,%1,%2,%3}, {%4,%5,%6,%7}, {%8,%9}, {%0,%1,%2,%3};"               \
        : "+f"((acc)[0]), "+f"((acc)[1]), "+f"((acc)[2]), "+f"((acc)[3])      \
        : "r"(a0), "r"(a1), "r"(a2), "r"(a3), "r"(b0), "r"(b1))

#define CP_ASYNC16(saddr, gptr)                                               \
    asm volatile("cp.async.cg.shared.global [%0], [%1], 16;"                  \
                 :: "r"(saddr), "l"(gptr))
#define CP_COMMIT() asm volatile("cp.async.commit_group;")
#define CP_WAIT(n)  asm volatile("cp.async.wait_group %0;" :: "n"(n))

// ============================================================================
// tf32 mma GEMM: C[M,N] = A[M,K] @ B[K,N]; CTA 128x128, 4 warps, warp 64x64
// ============================================================================
#define ASTRIDE 36
#define BSTRIDE 136
#define A_FLOATS (128 * ASTRIDE)
#define B_FLOATS (32 * BSTRIDE)
#define BUF_FLOATS (A_FLOATS + B_FLOATS)
#define GEMM_SMEM_BYTES (2 * BUF_FLOATS * 4)

template <int SCATTER>
__global__ __launch_bounds__(128, 2)
void mma_gemm_kernel(const float* __restrict__ A, const float* __restrict__ Bm,
                     float* __restrict__ C, int M, int N, int K)
{
    extern __shared__ __align__(16) float sm[];
    const int tid = threadIdx.x;
    const int wid = tid >> 5;
    const int lane = tid & 31;
    const int warp_m = wid >> 1;       // 0..1
    const int warp_n = wid & 1;        // 0..1
    const int bx = blockIdx.x, by = blockIdx.y;
    const int m0 = by * 128, n0 = bx * 128;
    const uint32_t sbase = smem_u32(sm);
    const int fr = lane >> 2, fc = lane & 3;

    const int a_m = tid >> 3, a_kq = tid & 7;     // +16 rows per i (8 iters)
    const int b_k = tid >> 5, b_nq = tid & 31;    // +4 k-rows per i (8 iters)

    const float* aG0 = A + (size_t)(m0 + a_m) * K + a_kq * 4;
    const float* bG0 = Bm + (size_t)b_k * N + n0 + b_nq * 4;
    const uint32_t aS0 = sbase + (uint32_t)(a_m * ASTRIDE + a_kq * 4) * 4;
    const uint32_t bS0 = sbase + (uint32_t)(A_FLOATS + b_k * BSTRIDE + b_nq * 4) * 4;

#define LOAD_TILE(kt, buf) do {                                               \
    const uint32_t off = (uint32_t)(buf) * (BUF_FLOATS * 4);                  \
    _Pragma("unroll")                                                         \
    for (int i = 0; i < 8; i++)                                               \
        CP_ASYNC16(aS0 + off + (uint32_t)(i * 16 * ASTRIDE) * 4,              \
                   aG0 + (size_t)(i * 16) * K + (kt) * 32);                   \
    _Pragma("unroll")                                                         \
    for (int i = 0; i < 8; i++)                                               \
        CP_ASYNC16(bS0 + off + (uint32_t)(i * 4 * BSTRIDE) * 4,               \
                   bG0 + (size_t)((kt) * 32 + i * 4) * N);                    \
    CP_COMMIT();                                                              \
} while (0)

    float acc[4][8][4];
#pragma unroll
    for (int mt = 0; mt < 4; mt++)
#pragma unroll
        for (int nt = 0; nt < 8; nt++)
#pragma unroll
            for (int r = 0; r < 4; r++) acc[mt][nt][r] = 0.f;

    const int KT = K / 32;
    LOAD_TILE(0, 0);

    for (int kt = 0; kt < KT; kt++) {
        const int buf = kt & 1;
        if (kt + 1 < KT) {
            LOAD_TILE(kt + 1, (kt + 1) & 1);
            CP_WAIT(1);
        } else {
            CP_WAIT(0);
        }
        __syncthreads();

        const float* As = sm + buf * BUF_FLOATS;
        const float* Bs = As + A_FLOATS;

#pragma unroll
        for (int s = 0; s < 4; s++) {
            const int kb = s * 8;
            uint32_t af[4][4], bf[8][2];
#pragma unroll
            for (int mt = 0; mt < 4; mt++) {
                const float* ap = As + (warp_m * 64 + mt * 16 + fr) * ASTRIDE + kb + fc;
                af[mt][0] = f2tf32(ap[0]);
                af[mt][1] = f2tf32(ap[8 * ASTRIDE]);
                af[mt][2] = f2tf32(ap[4]);
                af[mt][3] = f2tf32(ap[8 * ASTRIDE + 4]);
            }
#pragma unroll
            for (int nt = 0; nt < 8; nt++) {
                const float* bp = Bs + (kb + fc) * BSTRIDE + warp_n * 64 + nt * 8 + fr;
                bf[nt][0] = f2tf32(bp[0]);
                bf[nt][1] = f2tf32(bp[4 * BSTRIDE]);
            }
#pragma unroll
            for (int mt = 0; mt < 4; mt++)
#pragma unroll
                for (int nt = 0; nt < 8; nt++)
                    MMA_TF32(acc[mt][nt], af[mt][0], af[mt][1], af[mt][2], af[mt][3],
                             bf[nt][0], bf[nt][1]);
        }
        __syncthreads();
    }

    // epilogue
#pragma unroll
    for (int mt = 0; mt < 4; mt++) {
#pragma unroll
        for (int nt = 0; nt < 8; nt++) {
            const int r0 = m0 + warp_m * 64 + mt * 16 + fr;
            const int nloc = warp_n * 64 + nt * 8 + fc * 2;
            float2 v0 = make_float2(acc[mt][nt][0], acc[mt][nt][1]);
            float2 v1 = make_float2(acc[mt][nt][2], acc[mt][nt][3]);
            if (SCATTER) {
                const int b0_ = r0 >> 11, l0 = r0 & 2047;
                const int b1_ = (r0 + 8) >> 11, l1 = (r0 + 8) & 2047;
                *(float2*)(C + (((size_t)(b0_ * HH + bx)) * LL + l0) * DH + nloc) = v0;
                *(float2*)(C + (((size_t)(b1_ * HH + bx)) * LL + l1) * DH + nloc) = v1;
            } else {
                *(float2*)(C + (size_t)r0 * N + n0 + nloc) = v0;
                *(float2*)(C + (size_t)(r0 + 8) * N + n0 + nloc) = v1;
            }
        }
    }
#undef LOAD_TILE
}

// ---------------- RoPE + L2-normalize ----------------
__global__ __launch_bounds__(256)
void rope_norm_kernel(float* __restrict__ t)
{
    const int gw = (blockIdx.x * 256 + threadIdx.x) >> 5;
    const int lane = threadIdx.x & 31;
    const int pos = gw & (LL - 1);
    float* row = t + (size_t)gw * DH;

    const float invf0 = g_invf[lane];
    const float invf1 = g_invf[lane + 32];
    const float pf = (float)pos;
    float s0, c0, s1, c1;
    sincosf(pf * invf0, &s0, &c0);
    sincosf(pf * invf1, &s1, &c1);

    float2 x = ((const float2*)row)[lane];
    float2 y = ((const float2*)row)[lane + 32];
    const float r0 = x.x * c0 - x.y * s0;
    const float r1 = x.y * c0 + x.x * s0;
    const float r2 = y.x * c1 - y.y * s1;
    const float r3 = y.y * c1 + y.x * s1;

    float ss = r0 * r0 + r1 * r1 + r2 * r2 + r3 * r3;
#pragma unroll
    for (int off = 16; off > 0; off >>= 1)
        ss += __shfl_xor_sync(0xffffffffu, ss, off);
    const float inv = 1.0f / (sqrtf(ss) + 1e-6f);

    ((float2*)row)[lane]      = make_float2(r0 * inv, r1 * inv);
    ((float2*)row)[lane + 32] = make_float2(r2 * inv, r3 * inv);
}

// ============================================================================
// tensor-core causal flash attention: 64q-tile, 64k-tile, 4 warps (m16/warp)
// k_s: K[kpos][d] stride 132 (also Q staging); vt_s: V^T[d][kpos] stride 68;
// p_s: P[q][kpos] stride 68.  K/V/P fed to mma as tf32.
// ============================================================================
#define AKS 132
#define AVS 68
#define APS 68
#define AV_OFF (64 * AKS)                  // 8448
#define AP_OFF (AV_OFF + 128 * AVS)        // 17152
#define ATTN2_FLOATS (AP_OFF + 64 * APS)   // 21504
#define ATTN2_BYTES (ATTN2_FLOATS * 4)     // 86016

__global__ __launch_bounds__(128, 2)
void attn_mma_kernel(const float* __restrict__ scale_ptr)
{
    extern __shared__ __align__(16) float sm[];
    float* k_s  = sm;
    float* vt_s = sm + AV_OFF;
    float* p_s  = sm + AP_OFF;
    uint32_t* k_u  = (uint32_t*)k_s;
    uint32_t* vt_u = (uint32_t*)vt_s;

    const int qt = (int)gridDim.x - 1 - (int)blockIdx.x;   // heavy tiles first
    const int h = blockIdx.y, b = blockIdx.z;
    const int tid = threadIdx.x;
    const int wid = tid >> 5, lane = tid & 31;
    const int fr = lane >> 2, fc = lane & 3;
    const float sc2 = (*scale_ptr) * 1.4426950408889634f;  // fold log2(e)

    const size_t head_off = (size_t)(b * HH + h) * LL * DH;
    const float* qptr = g_q + head_off;
    const float* kptr = g_k + head_off;
    const float* vptr = g_v + head_off;
    const int q0 = qt * 64;

    const int lr = tid >> 1, lh = tid & 1;   // tile-loader slot: row, half

    // ---- stage Q into k_s, then preload A-frags (tf32) ----
    {
        const float* src = qptr + (size_t)(q0 + lr) * DH + lh * 64;
        float* dst = k_s + lr * AKS + lh * 64;
#pragma unroll
        for (int j = 0; j < 16; j++)
            *(float4*)(dst + j * 4) = *(const float4*)(src + j * 4);
    }
    __syncthreads();
    uint32_t qa[16][4];
    {
        const float* qp_ = k_s + (wid * 16 + fr) * AKS + fc;
#pragma unroll
        for (int s = 0; s < 16; s++) {
            qa[s][0] = f2tf32(qp_[s * 8]);
            qa[s][1] = f2tf32(qp_[8 * AKS + s * 8]);
            qa[s][2] = f2tf32(qp_[s * 8 + 4]);
            qa[s][3] = f2tf32(qp_[8 * AKS + s * 8 + 4]);
        }
    }

    float oacc[16][4];
#pragma unroll
    for (int nf = 0; nf < 16; nf++)
#pragma unroll
        for (int r = 0; r < 4; r++) oacc[nf][r] = 0.f;
    float m_[2] = {-1e30f, -1e30f};
    float l_[2] = {0.f, 0.f};

    const int row0 = q0 + wid * 16 + fr;

    for (int kt = 0; kt <= qt; kt++) {
        const int k0 = kt * 64;
        __syncthreads();   // protect k_s/vt_s from previous iteration readers
        {
            const float* ksrc = kptr + (size_t)(k0 + lr) * DH + lh * 64;
            const float* vsrc = vptr + (size_t)(k0 + lr) * DH + lh * 64;
            uint32_t* kdst = k_u + lr * AKS + lh * 64;
#pragma unroll
            for (int j = 0; j < 16; j++) {
                float4 kv = *(const float4*)(ksrc + j * 4);
                uint4 ku4 = make_uint4(f2tf32(kv.x), f2tf32(kv.y),
                                       f2tf32(kv.z), f2tf32(kv.w));
                *(uint4*)(kdst + j * 4) = ku4;
                float4 vv = *(const float4*)(vsrc + j * 4);
                const int d0 = lh * 64 + j * 4;
                vt_u[(d0 + 0) * AVS + lr] = f2tf32(vv.x);
                vt_u[(d0 + 1) * AVS + lr] = f2tf32(vv.y);
                vt_u[(d0 + 2) * AVS + lr] = f2tf32(vv.z);
                vt_u[(d0 + 3) * AVS + lr] = f2tf32(vv.w);
            }
        }
        __syncthreads();

        // ---- S = Q K^T ----
        float sacc[8][4];
#pragma unroll
        for (int j = 0; j < 8; j++)
#pragma unroll
            for (int r = 0; r < 4; r++) sacc[j][r] = 0.f;

#pragma unroll
        for (int s = 0; s < 16; s++) {
#pragma unroll
            for (int j = 0; j < 8; j++) {
                const uint32_t* kp_ = k_u + (8 * j + fr) * AKS + 8 * s + fc;
                uint32_t b0 = kp_[0];
                uint32_t b1 = kp_[4];
                MMA_TF32(sacc[j], qa[s][0], qa[s][1], qa[s][2], qa[s][3], b0, b1);
            }
        }

        // ---- mask (diagonal tile only) ----
        if (kt == qt) {
#pragma unroll
            for (int j = 0; j < 8; j++) {
                const int c0 = k0 + 8 * j + 2 * fc;
                if (c0 > row0)     sacc[j][0] = -1e30f;
                if (c0 + 1 > row0) sacc[j][1] = -1e30f;
                if (c0 > row0 + 8)     sacc[j][2] = -1e30f;
                if (c0 + 1 > row0 + 8) sacc[j][3] = -1e30f;
            }
        }

        // ---- online softmax (per row-pair) ----
#pragma unroll
        for (int r2 = 0; r2 < 2; r2++) {
            float rmax = -1e30f;
#pragma unroll
            for (int j = 0; j < 8; j++)
                rmax = fmaxf(rmax, fmaxf(sacc[j][2 * r2], sacc[j][2 * r2 + 1]));
            rmax = fmaxf(rmax, __shfl_xor_sync(0xffffffffu, rmax, 1));
            rmax = fmaxf(rmax, __shfl_xor_sync(0xffffffffu, rmax, 2));
            const float mn = fmaxf(m_[r2], rmax);
            const float fs = fast_exp2(sc2 * (m_[r2] - mn));
            const float base = sc2 * mn;
            float rs = 0.f;
            float* prow = p_s + (wid * 16 + fr + 8 * r2) * APS + 2 * fc;
#pragma unroll
            for (int j = 0; j < 8; j++) {
                float p0 = fast_exp2(__fmaf_rn(sc2, sacc[j][2 * r2], -base));
                float p1 = fast_exp2(__fmaf_rn(sc2, sacc[j][2 * r2 + 1], -base));
                rs += p0 + p1;
                prow[8 * j]     = p0;
                prow[8 * j + 1] = p1;
            }
            rs += __shfl_xor_sync(0xffffffffu, rs, 1);
            rs += __shfl_xor_sync(0xffffffffu, rs, 2);
            l_[r2] = l_[r2] * fs + rs;
            m_[r2] = mn;
#pragma unroll
            for (int nf = 0; nf < 16; nf++) {
                oacc[nf][2 * r2]     *= fs;
                oacc[nf][2 * r2 + 1] *= fs;
            }
        }
        __syncwarp();

        // ---- O += P V ----
#pragma unroll
        for (int s2 = 0; s2 < 8; s2++) {
            const float* pp = p_s + (wid * 16 + fr) * APS + 8 * s2 + fc;
            uint32_t a0 = f2tf32(pp[0]);
            uint32_t a1 = f2tf32(pp[8 * APS]);
            uint32_t a2 = f2tf32(pp[4]);
            uint32_t a3 = f2tf32(pp[8 * APS + 4]);
#pragma unroll
            for (int nf = 0; nf < 16; nf++) {
                const uint32_t* vp_ = vt_u + (8 * nf + fr) * AVS + 8 * s2 + fc;
                uint32_t b0 = vp_[0];
                uint32_t b1 = vp_[4];
                MMA_TF32(oacc[nf], a0, a1, a2, a3, b0, b1);
            }
        }
        __syncwarp();
    }

    // ---- epilogue: normalize + write [b][l][h*128+d] ----
    const float inv0 = 1.f / l_[0];
    const float inv1 = 1.f / l_[1];
    float* d0p = g_attn + ((size_t)(b * LL + row0)) * DD + h * DH + 2 * fc;
    float* d1p = g_attn + ((size_t)(b * LL + row0 + 8)) * DD + h * DH + 2 * fc;
#pragma unroll
    for (int nf = 0; nf < 16; nf++) {
        *(float2*)(d0p + 8 * nf) = make_float2(oacc[nf][0] * inv0, oacc[nf][1] * inv0);
        *(float2*)(d1p + 8 * nf) = make_float2(oacc[nf][2] * inv1, oacc[nf][3] * inv1);
    }
}

// ---------------- launch ----------------
extern "C" void kernel_launch(void* const* d_in, const int* in_sizes, int n_in,
                              void* d_out, int out_size)
{
    const float* x     = (const float*)d_in[0];
    const float* Wq    = (const float*)d_in[1];
    const float* Wk    = (const float*)d_in[2];
    const float* Wv    = (const float*)d_in[3];
    const float* Wout  = (const float*)d_in[4];
    const float* scale = (const float*)d_in[5];
    float* out = (float*)d_out;

    float *qp, *kp, *vp, *ap;
    cudaGetSymbolAddress((void**)&qp, g_q);
    cudaGetSymbolAddress((void**)&kp, g_k);
    cudaGetSymbolAddress((void**)&vp, g_v);
    cudaGetSymbolAddress((void**)&ap, g_attn);

    build_invf_kernel<<<1, 64>>>();

    const int M = BB * LL;  // 4096
    dim3 gemm_grid(DD / 128, M / 128);

    cudaFuncSetAttribute(mma_gemm_kernel<1>, cudaFuncAttributeMaxDynamicSharedMemorySize,
                         GEMM_SMEM_BYTES);
    cudaFuncSetAttribute(mma_gemm_kernel<0>, cudaFuncAttributeMaxDynamicSharedMemorySize,
                         GEMM_SMEM_BYTES);
    cudaFuncSetAttribute(attn_mma_kernel, cudaFuncAttributeMaxDynamicSharedMemorySize,
                         ATTN2_BYTES);

    mma_gemm_kernel<1><<<gemm_grid, 128, GEMM_SMEM_BYTES>>>(x, Wq, qp, M, DD, DD);
    mma_gemm_kernel<1><<<gemm_grid, 128, GEMM_SMEM_BYTES>>>(x, Wk, kp, M, DD, DD);
    mma_gemm_kernel<1><<<gemm_grid, 128, GEMM_SMEM_BYTES>>>(x, Wv, vp, M, DD, DD);

    const int rope_blocks = (BB * HH * LL) / 8;
    rope_norm_kernel<<<rope_blocks, 256>>>(qp);
    rope_norm_kernel<<<rope_blocks, 256>>>(kp);

    attn_mma_kernel<<<dim3(LL / 64, HH, BB), 128, ATTN2_BYTES>>>(scale);

    mma_gemm_kernel<0><<<gemm_grid, 128, GEMM_SMEM_BYTES>>>(ap, Wout, out, M, DD, DD);
}

// round 9
// speedup vs baseline: 3.4557x; 1.0666x over previous
#include <cuda_runtime.h>
#include <cstdint>
#include <cmath>

#define BB 2
#define LL 2048
#define DD 2048
#define HH 16
#define DH 128

// ---------------- scratch ----------------
__device__ float    g_q[(size_t)BB * HH * LL * DH];     // fp32 after GEMM, tf32 bits after rope
__device__ float    g_k[(size_t)BB * HH * LL * DH];
__device__ uint32_t g_v[(size_t)BB * HH * LL * DH];     // tf32 bits (GEMM epilogue converts)
__device__ uint32_t g_attn[(size_t)BB * LL * DD];       // tf32 bits (attn epilogue converts)
__device__ uint32_t g_xc[(size_t)BB * LL * DD];         // x as tf32 bits
__device__ uint32_t g_wqc[(size_t)DD * DD];
__device__ uint32_t g_wkc[(size_t)DD * DD];
__device__ uint32_t g_wvc[(size_t)DD * DD];
__device__ uint32_t g_woc[(size_t)DD * DD];
__device__ float    g_invf[64];

__global__ void build_invf_kernel() {
    int i = threadIdx.x;
    if (i < 64) {
        double e = (double)(2 * i) / 128.0;
        g_invf[i] = (float)pow(500000.0, -e);
    }
}

__device__ __forceinline__ uint32_t smem_u32(const void* p) {
    uint32_t a;
    asm("{ .reg .u64 t; cvta.to.shared.u64 t, %1; cvt.u32.u64 %0, t; }"
        : "=r"(a) : "l"(p));
    return a;
}

__device__ __forceinline__ uint32_t f2tf32(float f) {
    uint32_t u;
    asm("cvt.rna.tf32.f32 %0, %1;" : "=r"(u) : "f"(f));
    return u;
}

__device__ __forceinline__ float fast_exp2(float x) {
    float r;
    asm("ex2.approx.ftz.f32 %0, %1;" : "=f"(r) : "f"(x));
    return r;
}

#define MMA_TF32(acc, a0, a1, a2, a3, b0, b1)                                 \
    asm volatile(                                                             \
        "mma.sync.aligned.m16n8k8.row.col.f32.tf32.tf32.f32 "                 \
        "{%0,%1,%2,%3}, {%4,%5,%6,%7}, {%8,%9}, {%0,%1,%2,%3};"               \
        : "+f"((acc)[0]), "+f"((acc)[1]), "+f"((acc)[2]), "+f"((acc)[3])      \
        : "r"(a0), "r"(a1), "r"(a2), "r"(a3), "r"(b0), "r"(b1))

#define CP_ASYNC16(saddr, gptr)                                               \
    asm volatile("cp.async.cg.shared.global [%0], [%1], 16;"                  \
                 :: "r"(saddr), "l"(gptr))
#define CP_COMMIT() asm volatile("cp.async.commit_group;")
#define CP_WAIT(n)  asm volatile("cp.async.wait_group %0;" :: "n"(n))

// ---------------- fp32 -> tf32-bits bulk converter ----------------
__global__ __launch_bounds__(256)
void cvt_kernel(const float* __restrict__ s, uint32_t* __restrict__ d, int n4)
{
    int i = blockIdx.x * 256 + threadIdx.x;
    if (i < n4) {
        float4 v = ((const float4*)s)[i];
        ((uint4*)d)[i] = make_uint4(f2tf32(v.x), f2tf32(v.y), f2tf32(v.z), f2tf32(v.w));
    }
}

// ============================================================================
// tf32 mma GEMM on pre-converted bits: CTA 128x128, 8 warps (2m x 4n), warp 64x32
// MODE 0: C = A@B0 plain float out.  MODE 1: fused QKV (bx>>4 selects matrix)
// ============================================================================
#define ASTRIDE 36
#define BSTRIDE 136
#define A_FLOATS (128 * ASTRIDE)
#define B_FLOATS (32 * BSTRIDE)
#define BUF_FLOATS (A_FLOATS + B_FLOATS)
#define GEMM_SMEM_BYTES (2 * BUF_FLOATS * 4)

template <int MODE>
__global__ __launch_bounds__(256, 2)
void mma_gemm_kernel(const uint32_t* __restrict__ A,
                     const uint32_t* __restrict__ B0,
                     const uint32_t* __restrict__ B1,
                     const uint32_t* __restrict__ B2,
                     float* __restrict__ Cq, float* __restrict__ Ck,
                     uint32_t* __restrict__ Cv, float* __restrict__ Cout,
                     int M, int N, int K)
{
    extern __shared__ __align__(16) uint32_t smu[];
    const int tid = threadIdx.x;
    const int wid = tid >> 5;
    const int lane = tid & 31;
    const int warp_m = wid >> 2;       // 0..1
    const int warp_n = wid & 3;        // 0..3
    const int by = blockIdx.y;
    int bxm = blockIdx.x, mid = 0;
    const uint32_t* Bm;
    if (MODE == 1) {
        mid = bxm >> 4;
        bxm &= 15;
        Bm = (mid == 0) ? B0 : (mid == 1) ? B1 : B2;
    } else {
        Bm = B0;
    }
    const int m0 = by * 128, n0 = bxm * 128;
    const uint32_t sbase = smem_u32(smu);
    const int fr = lane >> 2, fc = lane & 3;

    const int a_m = tid >> 3, a_kq = tid & 7;     // +32 rows per i
    const int b_k = tid >> 5, b_nq = tid & 31;    // +8 k-rows per i

    const uint32_t* aG0 = A + (size_t)(m0 + a_m) * K + a_kq * 4;
    const uint32_t* bG0 = Bm + (size_t)b_k * N + n0 + b_nq * 4;
    const uint32_t aS0 = sbase + (uint32_t)(a_m * ASTRIDE + a_kq * 4) * 4;
    const uint32_t bS0 = sbase + (uint32_t)(A_FLOATS + b_k * BSTRIDE + b_nq * 4) * 4;

#define LOAD_TILE(kt, buf) do {                                               \
    const uint32_t off = (uint32_t)(buf) * (BUF_FLOATS * 4);                  \
    _Pragma("unroll")                                                         \
    for (int i = 0; i < 4; i++)                                               \
        CP_ASYNC16(aS0 + off + (uint32_t)(i * 32 * ASTRIDE) * 4,              \
                   aG0 + (size_t)(i * 32) * K + (kt) * 32);                   \
    _Pragma("unroll")                                                         \
    for (int i = 0; i < 4; i++)                                               \
        CP_ASYNC16(bS0 + off + (uint32_t)(i * 8 * BSTRIDE) * 4,               \
                   bG0 + (size_t)((kt) * 32 + i * 8) * N);                    \
    CP_COMMIT();                                                              \
} while (0)

    float acc[4][4][4];
#pragma unroll
    for (int mt = 0; mt < 4; mt++)
#pragma unroll
        for (int nt = 0; nt < 4; nt++)
#pragma unroll
            for (int r = 0; r < 4; r++) acc[mt][nt][r] = 0.f;

    const int KT = K / 32;
    LOAD_TILE(0, 0);

    for (int kt = 0; kt < KT; kt++) {
        const int buf = kt & 1;
        if (kt + 1 < KT) {
            LOAD_TILE(kt + 1, (kt + 1) & 1);
            CP_WAIT(1);
        } else {
            CP_WAIT(0);
        }
        __syncthreads();

        const uint32_t* As = smu + buf * BUF_FLOATS;
        const uint32_t* Bs = As + A_FLOATS;

#pragma unroll
        for (int s = 0; s < 4; s++) {
            const int kb = s * 8;
            uint32_t af[4][4], bf[4][2];
#pragma unroll
            for (int mt = 0; mt < 4; mt++) {
                const uint32_t* ap = As + (warp_m * 64 + mt * 16 + fr) * ASTRIDE + kb + fc;
                af[mt][0] = ap[0];
                af[mt][1] = ap[8 * ASTRIDE];
                af[mt][2] = ap[4];
                af[mt][3] = ap[8 * ASTRIDE + 4];
            }
#pragma unroll
            for (int nt = 0; nt < 4; nt++) {
                const uint32_t* bp = Bs + (kb + fc) * BSTRIDE + warp_n * 32 + nt * 8 + fr;
                bf[nt][0] = bp[0];
                bf[nt][1] = bp[4 * BSTRIDE];
            }
#pragma unroll
            for (int mt = 0; mt < 4; mt++)
#pragma unroll
                for (int nt = 0; nt < 4; nt++)
                    MMA_TF32(acc[mt][nt], af[mt][0], af[mt][1], af[mt][2], af[mt][3],
                             bf[nt][0], bf[nt][1]);
        }
        __syncthreads();
    }

    // epilogue
#pragma unroll
    for (int mt = 0; mt < 4; mt++) {
#pragma unroll
        for (int nt = 0; nt < 4; nt++) {
            const int r0 = m0 + warp_m * 64 + mt * 16 + fr;
            const int nloc = warp_n * 32 + nt * 8 + fc * 2;
            float2 v0 = make_float2(acc[mt][nt][0], acc[mt][nt][1]);
            float2 v1 = make_float2(acc[mt][nt][2], acc[mt][nt][3]);
            if (MODE == 1) {
                const int b0_ = r0 >> 11, l0 = r0 & 2047;
                const int b1_ = (r0 + 8) >> 11, l1 = (r0 + 8) & 2047;
                const size_t o0 = (((size_t)(b0_ * HH + bxm)) * LL + l0) * DH + nloc;
                const size_t o1 = (((size_t)(b1_ * HH + bxm)) * LL + l1) * DH + nloc;
                if (mid == 2) {
                    *(uint2*)(Cv + o0) = make_uint2(f2tf32(v0.x), f2tf32(v0.y));
                    *(uint2*)(Cv + o1) = make_uint2(f2tf32(v1.x), f2tf32(v1.y));
                } else {
                    float* Ct = (mid == 0) ? Cq : Ck;
                    *(float2*)(Ct + o0) = v0;
                    *(float2*)(Ct + o1) = v1;
                }
            } else {
                *(float2*)(Cout + (size_t)r0 * N + n0 + nloc) = v0;
                *(float2*)(Cout + (size_t)(r0 + 8) * N + n0 + nloc) = v1;
            }
        }
    }
#undef LOAD_TILE
}

// ---------------- RoPE + L2-normalize; writes tf32 bits in place ----------------
__global__ __launch_bounds__(256)
void rope_norm_kernel(float* __restrict__ t)
{
    const int gw = (blockIdx.x * 256 + threadIdx.x) >> 5;
    const int lane = threadIdx.x & 31;
    const int pos = gw & (LL - 1);
    float* row = t + (size_t)gw * DH;

    const float invf0 = g_invf[lane];
    const float invf1 = g_invf[lane + 32];
    const float pf = (float)pos;
    float s0, c0, s1, c1;
    sincosf(pf * invf0, &s0, &c0);
    sincosf(pf * invf1, &s1, &c1);

    float2 x = ((const float2*)row)[lane];
    float2 y = ((const float2*)row)[lane + 32];
    const float r0 = x.x * c0 - x.y * s0;
    const float r1 = x.y * c0 + x.x * s0;
    const float r2 = y.x * c1 - y.y * s1;
    const float r3 = y.y * c1 + y.x * s1;

    float ss = r0 * r0 + r1 * r1 + r2 * r2 + r3 * r3;
#pragma unroll
    for (int off = 16; off > 0; off >>= 1)
        ss += __shfl_xor_sync(0xffffffffu, ss, off);
    const float inv = 1.0f / (sqrtf(ss) + 1e-6f);

    uint32_t* rowu = (uint32_t*)row;
    ((uint2*)rowu)[lane]      = make_uint2(f2tf32(r0 * inv), f2tf32(r1 * inv));
    ((uint2*)rowu)[lane + 32] = make_uint2(f2tf32(r2 * inv), f2tf32(r3 * inv));
}

// ============================================================================
// tensor-core causal flash attention on tf32 bits
// k_s: K[kpos][d] stride 132 (also Q staging); v_s: V[kpos][d] stride 136;
// p_s: P[q][kpos] bits stride 68.
// ============================================================================
#define AKS 132
#define AVS 136
#define APS 68
#define AV_OFF (64 * AKS)                  // 8448
#define AP_OFF (AV_OFF + 64 * AVS)         // 17152
#define ATTN2_U32 (AP_OFF + 64 * APS)      // 21504
#define ATTN2_BYTES (ATTN2_U32 * 4)        // 86016

__global__ __launch_bounds__(128, 2)
void attn_mma_kernel(const float* __restrict__ scale_ptr)
{
    extern __shared__ __align__(16) uint32_t smu[];
    uint32_t* k_u = smu;
    uint32_t* v_u = smu + AV_OFF;
    uint32_t* p_u = smu + AP_OFF;

    const int qt = (int)gridDim.x - 1 - (int)blockIdx.x;   // heavy tiles first
    const int h = blockIdx.y, b = blockIdx.z;
    const int tid = threadIdx.x;
    const int wid = tid >> 5, lane = tid & 31;
    const int fr = lane >> 2, fc = lane & 3;
    const float sc2 = (*scale_ptr) * 1.4426950408889634f;  // fold log2(e)

    const size_t head_off = (size_t)(b * HH + h) * LL * DH;
    const uint32_t* qptr = (const uint32_t*)g_q + head_off;
    const uint32_t* kptr = (const uint32_t*)g_k + head_off;
    const uint32_t* vptr = g_v + head_off;
    const int q0 = qt * 64;

    const int lr = tid >> 1, lh = tid & 1;   // loader: row, half

    // ---- stage Q bits into k_s, preload A-frags ----
    {
        const uint32_t* src = qptr + (size_t)(q0 + lr) * DH + lh * 64;
        uint32_t* dst = k_u + lr * AKS + lh * 64;
#pragma unroll
        for (int j = 0; j < 16; j++)
            *(uint4*)(dst + j * 4) = *(const uint4*)(src + j * 4);
    }
    __syncthreads();
    uint32_t qa[16][4];
    {
        const uint32_t* qp_ = k_u + (wid * 16 + fr) * AKS + fc;
#pragma unroll
        for (int s = 0; s < 16; s++) {
            qa[s][0] = qp_[s * 8];
            qa[s][1] = qp_[8 * AKS + s * 8];
            qa[s][2] = qp_[s * 8 + 4];
            qa[s][3] = qp_[8 * AKS + s * 8 + 4];
        }
    }

    float oacc[16][4];
#pragma unroll
    for (int nf = 0; nf < 16; nf++)
#pragma unroll
        for (int r = 0; r < 4; r++) oacc[nf][r] = 0.f;
    float m_[2] = {-1e30f, -1e30f};
    float l_[2] = {0.f, 0.f};

    const int row0 = q0 + wid * 16 + fr;

    for (int kt = 0; kt <= qt; kt++) {
        const int k0 = kt * 64;
        __syncthreads();
        {
            const uint32_t* ksrc = kptr + (size_t)(k0 + lr) * DH + lh * 64;
            const uint32_t* vsrc = vptr + (size_t)(k0 + lr) * DH + lh * 64;
            uint32_t* kdst = k_u + lr * AKS + lh * 64;
            uint32_t* vdst = v_u + lr * AVS + lh * 64;
#pragma unroll
            for (int j = 0; j < 16; j++) {
                *(uint4*)(kdst + j * 4) = *(const uint4*)(ksrc + j * 4);
                *(uint4*)(vdst + j * 4) = *(const uint4*)(vsrc + j * 4);
            }
        }
        __syncthreads();

        // ---- S = Q K^T ----
        float sacc[8][4];
#pragma unroll
        for (int j = 0; j < 8; j++)
#pragma unroll
            for (int r = 0; r < 4; r++) sacc[j][r] = 0.f;

#pragma unroll
        for (int s = 0; s < 16; s++) {
#pragma unroll
            for (int j = 0; j < 8; j++) {
                const uint32_t* kp_ = k_u + (8 * j + fr) * AKS + 8 * s + fc;
                MMA_TF32(sacc[j], qa[s][0], qa[s][1], qa[s][2], qa[s][3],
                         kp_[0], kp_[4]);
            }
        }

        // ---- mask (diagonal tile only) ----
        if (kt == qt) {
#pragma unroll
            for (int j = 0; j < 8; j++) {
                const int c0 = k0 + 8 * j + 2 * fc;
                if (c0 > row0)     sacc[j][0] = -1e30f;
                if (c0 + 1 > row0) sacc[j][1] = -1e30f;
                if (c0 > row0 + 8)     sacc[j][2] = -1e30f;
                if (c0 + 1 > row0 + 8) sacc[j][3] = -1e30f;
            }
        }

        // ---- online softmax ----
#pragma unroll
        for (int r2 = 0; r2 < 2; r2++) {
            float rmax = -1e30f;
#pragma unroll
            for (int j = 0; j < 8; j++)
                rmax = fmaxf(rmax, fmaxf(sacc[j][2 * r2], sacc[j][2 * r2 + 1]));
            rmax = fmaxf(rmax, __shfl_xor_sync(0xffffffffu, rmax, 1));
            rmax = fmaxf(rmax, __shfl_xor_sync(0xffffffffu, rmax, 2));
            const float mn = fmaxf(m_[r2], rmax);
            const float fs = fast_exp2(sc2 * (m_[r2] - mn));
            const float base = sc2 * mn;
            float rs = 0.f;
            uint32_t* prow = p_u + (wid * 16 + fr + 8 * r2) * APS + 2 * fc;
#pragma unroll
            for (int j = 0; j < 8; j++) {
                float p0 = fast_exp2(__fmaf_rn(sc2, sacc[j][2 * r2], -base));
                float p1 = fast_exp2(__fmaf_rn(sc2, sacc[j][2 * r2 + 1], -base));
                rs += p0 + p1;
                prow[8 * j]     = f2tf32(p0);
                prow[8 * j + 1] = f2tf32(p1);
            }
            rs += __shfl_xor_sync(0xffffffffu, rs, 1);
            rs += __shfl_xor_sync(0xffffffffu, rs, 2);
            l_[r2] = l_[r2] * fs + rs;
            m_[r2] = mn;
#pragma unroll
            for (int nf = 0; nf < 16; nf++) {
                oacc[nf][2 * r2]     *= fs;
                oacc[nf][2 * r2 + 1] *= fs;
            }
        }
        __syncwarp();

        // ---- O += P V ----
#pragma unroll
        for (int s2 = 0; s2 < 8; s2++) {
            const uint32_t* pp = p_u + (wid * 16 + fr) * APS + 8 * s2 + fc;
            uint32_t a0 = pp[0];
            uint32_t a1 = pp[8 * APS];
            uint32_t a2 = pp[4];
            uint32_t a3 = pp[8 * APS + 4];
#pragma unroll
            for (int nf = 0; nf < 16; nf++) {
                const uint32_t* vp_ = v_u + (8 * s2 + fc) * AVS + 8 * nf + fr;
                MMA_TF32(oacc[nf], a0, a1, a2, a3, vp_[0], vp_[4 * AVS]);
            }
        }
        __syncwarp();
    }

    // ---- epilogue: normalize + write tf32 bits [b][l][h*128+d] ----
    const float inv0 = 1.f / l_[0];
    const float inv1 = 1.f / l_[1];
    uint32_t* d0p = g_attn + ((size_t)(b * LL + row0)) * DD + h * DH + 2 * fc;
    uint32_t* d1p = g_attn + ((size_t)(b * LL + row0 + 8)) * DD + h * DH + 2 * fc;
#pragma unroll
    for (int nf = 0; nf < 16; nf++) {
        *(uint2*)(d0p + 8 * nf) = make_uint2(f2tf32(oacc[nf][0] * inv0),
                                             f2tf32(oacc[nf][1] * inv0));
        *(uint2*)(d1p + 8 * nf) = make_uint2(f2tf32(oacc[nf][2] * inv1),
                                             f2tf32(oacc[nf][3] * inv1));
    }
}

// ---------------- launch ----------------
extern "C" void kernel_launch(void* const* d_in, const int* in_sizes, int n_in,
                              void* d_out, int out_size)
{
    const float* x     = (const float*)d_in[0];
    const float* Wq    = (const float*)d_in[1];
    const float* Wk    = (const float*)d_in[2];
    const float* Wv    = (const float*)d_in[3];
    const float* Wout  = (const float*)d_in[4];
    const float* scale = (const float*)d_in[5];
    float* out = (float*)d_out;

    float *qp, *kp;
    uint32_t *vp, *ap, *xc, *wqc, *wkc, *wvc, *woc;
    cudaGetSymbolAddress((void**)&qp,  g_q);
    cudaGetSymbolAddress((void**)&kp,  g_k);
    cudaGetSymbolAddress((void**)&vp,  g_v);
    cudaGetSymbolAddress((void**)&ap,  g_attn);
    cudaGetSymbolAddress((void**)&xc,  g_xc);
    cudaGetSymbolAddress((void**)&wqc, g_wqc);
    cudaGetSymbolAddress((void**)&wkc, g_wkc);
    cudaGetSymbolAddress((void**)&wvc, g_wvc);
    cudaGetSymbolAddress((void**)&woc, g_woc);

    build_invf_kernel<<<1, 64>>>();

    const int M = BB * LL;           // 4096
    const int XN4 = (M * DD) / 4;    // 2,097,152
    const int WN4 = (DD * DD) / 4;   // 1,048,576
    cvt_kernel<<<XN4 / 256, 256>>>(x, xc, XN4);
    cvt_kernel<<<WN4 / 256, 256>>>(Wq, wqc, WN4);
    cvt_kernel<<<WN4 / 256, 256>>>(Wk, wkc, WN4);
    cvt_kernel<<<WN4 / 256, 256>>>(Wv, wvc, WN4);
    cvt_kernel<<<WN4 / 256, 256>>>(Wout, woc, WN4);

    cudaFuncSetAttribute(mma_gemm_kernel<0>, cudaFuncAttributeMaxDynamicSharedMemorySize,
                         GEMM_SMEM_BYTES);
    cudaFuncSetAttribute(mma_gemm_kernel<1>, cudaFuncAttributeMaxDynamicSharedMemorySize,
                         GEMM_SMEM_BYTES);
    cudaFuncSetAttribute(attn_mma_kernel, cudaFuncAttributeMaxDynamicSharedMemorySize,
                         ATTN2_BYTES);

    // fused QKV: grid.x = 48 (16 n-blocks x 3 matrices)
    mma_gemm_kernel<1><<<dim3(48, M / 128), 256, GEMM_SMEM_BYTES>>>(
        xc, wqc, wkc, wvc, qp, kp, vp, nullptr, M, DD, DD);

    const int rope_blocks = (BB * HH * LL) / 8;
    rope_norm_kernel<<<rope_blocks, 256>>>(qp);
    rope_norm_kernel<<<rope_blocks, 256>>>(kp);

    attn_mma_kernel<<<dim3(LL / 64, HH, BB), 128, ATTN2_BYTES>>>(scale);

    mma_gemm_kernel<0><<<dim3(16, M / 128), 256, GEMM_SMEM_BYTES>>>(
        ap, woc, nullptr, nullptr, nullptr, nullptr, nullptr, out, M, DD, DD);
}

// round 10
// speedup vs baseline: 3.5841x; 1.0372x over previous
#include <cuda_runtime.h>
#include <cstdint>
#include <cmath>

#define BB 2
#define LL 2048
#define DD 2048
#define HH 16
#define DH 128

// ---------------- scratch ----------------
__device__ float    g_q[(size_t)BB * HH * LL * DH];     // fp32 after GEMM, tf32 bits after rope
__device__ float    g_k[(size_t)BB * HH * LL * DH];
__device__ uint32_t g_v[(size_t)BB * HH * LL * DH];     // tf32 bits, TRANSPOSED: [b][h][d][l]
__device__ uint32_t g_attn[(size_t)BB * LL * DD];       // tf32 bits
__device__ uint32_t g_xc[(size_t)BB * LL * DD];         // x as tf32 bits
__device__ uint32_t g_wqc[(size_t)DD * DD];             // W^T as tf32 bits  [n][k]
__device__ uint32_t g_wkc[(size_t)DD * DD];
__device__ uint32_t g_wvc[(size_t)DD * DD];
__device__ uint32_t g_woc[(size_t)DD * DD];
__device__ float    g_invf[64];

__global__ void build_invf_kernel() {
    int i = threadIdx.x;
    if (i < 64) {
        double e = (double)(2 * i) / 128.0;
        g_invf[i] = (float)pow(500000.0, -e);
    }
}

__device__ __forceinline__ uint32_t smem_u32(const void* p) {
    uint32_t a;
    asm("{ .reg .u64 t; cvta.to.shared.u64 t, %1; cvt.u32.u64 %0, t; }"
        : "=r"(a) : "l"(p));
    return a;
}

__device__ __forceinline__ uint32_t f2tf32(float f) {
    uint32_t u;
    asm("cvt.rna.tf32.f32 %0, %1;" : "=r"(u) : "f"(f));
    return u;
}

__device__ __forceinline__ float fast_exp2(float x) {
    float r;
    asm("ex2.approx.ftz.f32 %0, %1;" : "=f"(r) : "f"(x));
    return r;
}

#define MMA_TF32(acc, a0, a1, a2, a3, b0, b1)                                 \
    asm volatile(                                                             \
        "mma.sync.aligned.m16n8k8.row.col.f32.tf32.tf32.f32 "                 \
        "{%0,%1,%2,%3}, {%4,%5,%6,%7}, {%8,%9}, {%0,%1,%2,%3};"               \
        : "+f"((acc)[0]), "+f"((acc)[1]), "+f"((acc)[2]), "+f"((acc)[3])      \
        : "r"(a0), "r"(a1), "r"(a2), "r"(a3), "r"(b0), "r"(b1))

// x4 ldmatrix: thread lane>>3 selects matrix; per-thread addr = row (lane&7) of it
#define LDSM_X4(r0, r1, r2, r3, addr)                                         \
    asm volatile("ldmatrix.sync.aligned.m8n8.x4.shared.b16 {%0,%1,%2,%3}, [%4];" \
                 : "=r"(r0), "=r"(r1), "=r"(r2), "=r"(r3) : "r"(addr))

#define CP_ASYNC16(saddr, gptr)                                               \
    asm volatile("cp.async.cg.shared.global [%0], [%1], 16;"                  \
                 :: "r"(saddr), "l"(gptr))
#define CP_COMMIT() asm volatile("cp.async.commit_group;")
#define CP_WAIT(n)  asm volatile("cp.async.wait_group %0;" :: "n"(n))

// ---------------- fp32 -> tf32-bits converters ----------------
__global__ __launch_bounds__(256)
void cvt_kernel(const float* __restrict__ s, uint32_t* __restrict__ d, int n4)
{
    int i = blockIdx.x * 256 + threadIdx.x;
    if (i < n4) {
        float4 v = ((const float4*)s)[i];
        ((uint4*)d)[i] = make_uint4(f2tf32(v.x), f2tf32(v.y), f2tf32(v.z), f2tf32(v.w));
    }
}

// transpose + convert: W [k][n] fp32 -> Wt [n][k] tf32 bits
__global__ __launch_bounds__(256)
void cvt_t_kernel(const float* __restrict__ s, uint32_t* __restrict__ d)
{
    __shared__ uint32_t tile[32][33];
    const int tx = threadIdx.x & 31, ty = threadIdx.x >> 5;
    const int c0 = blockIdx.x * 32, r0 = blockIdx.y * 32;
#pragma unroll
    for (int i = 0; i < 4; i++)
        tile[ty + i * 8][tx] = f2tf32(s[(size_t)(r0 + ty + i * 8) * DD + c0 + tx]);
    __syncthreads();
#pragma unroll
    for (int i = 0; i < 4; i++)
        d[(size_t)(c0 + ty + i * 8) * DD + r0 + tx] = tile[tx][ty + i * 8];
}

// ============================================================================
// tf32 mma GEMM, ldmatrix feeds: C[M,N] = A[M,K] @ Bt^T  (Bt is [n][k])
// CTA 128x128, 8 warps (2m x 4n), warp 64x32.  A smem [m][k], B smem [n][k].
// ============================================================================
#define ASTRIDE 36
#define A_FLOATS (128 * ASTRIDE)          // 4608
#define B_FLOATS (128 * ASTRIDE)          // 4608
#define BUF_FLOATS (A_FLOATS + B_FLOATS)  // 9216
#define GEMM_SMEM_BYTES (2 * BUF_FLOATS * 4)  // 73728

template <int MODE>
__global__ __launch_bounds__(256, 2)
void mma_gemm_kernel(const uint32_t* __restrict__ A,
                     const uint32_t* __restrict__ B0,
                     const uint32_t* __restrict__ B1,
                     const uint32_t* __restrict__ B2,
                     float* __restrict__ Cq, float* __restrict__ Ck,
                     uint32_t* __restrict__ Cv, float* __restrict__ Cout,
                     int M, int N, int K)
{
    extern __shared__ __align__(16) uint32_t smu[];
    const int tid = threadIdx.x;
    const int wid = tid >> 5;
    const int lane = tid & 31;
    const int warp_m = wid >> 2;       // 0..1
    const int warp_n = wid & 3;        // 0..3
    const int by = blockIdx.y;
    int bxm = blockIdx.x, mid = 0;
    const uint32_t* Bm;
    if (MODE == 1) {
        mid = bxm >> 4;
        bxm &= 15;
        Bm = (mid == 0) ? B0 : (mid == 1) ? B1 : B2;
    } else {
        Bm = B0;
    }
    const int m0 = by * 128, n0 = bxm * 128;
    const uint32_t sbase = smem_u32(smu);
    const int fr = lane >> 2, fc = lane & 3;
    const int t3 = lane >> 3, rr = lane & 7;

    // ldmatrix per-thread row/col offsets
    const int a_row = warp_m * 64 + (t3 & 1) * 8 + rr;   // + mt*16
    const int a_col = (t3 >> 1) * 4;                      // + kb
    const int b_row = warp_n * 32 + (t3 >> 1) * 8 + rr;  // + ntp*16
    const int b_col = (t3 & 1) * 4;                       // + kb

    // loaders: 8 threads per row, 32 rows per pass, 4 passes
    const int l_r = tid >> 3, l_kq = tid & 7;
    const uint32_t* aG0 = A + (size_t)(m0 + l_r) * K + l_kq * 4;
    const uint32_t* bG0 = Bm + (size_t)(n0 + l_r) * K + l_kq * 4;
    const uint32_t aS0 = sbase + (uint32_t)(l_r * ASTRIDE + l_kq * 4) * 4;
    const uint32_t bS0 = sbase + (uint32_t)(A_FLOATS + l_r * ASTRIDE + l_kq * 4) * 4;

#define LOAD_TILE(kt, buf) do {                                               \
    const uint32_t off = (uint32_t)(buf) * (BUF_FLOATS * 4);                  \
    _Pragma("unroll")                                                         \
    for (int i = 0; i < 4; i++)                                               \
        CP_ASYNC16(aS0 + off + (uint32_t)(i * 32 * ASTRIDE) * 4,              \
                   aG0 + (size_t)(i * 32) * K + (kt) * 32);                   \
    _Pragma("unroll")                                                         \
    for (int i = 0; i < 4; i++)                                               \
        CP_ASYNC16(bS0 + off + (uint32_t)(i * 32 * ASTRIDE) * 4,              \
                   bG0 + (size_t)(i * 32) * K + (kt) * 32);                   \
    CP_COMMIT();                                                              \
} while (0)

    float acc[4][4][4];
#pragma unroll
    for (int mt = 0; mt < 4; mt++)
#pragma unroll
        for (int nt = 0; nt < 4; nt++)
#pragma unroll
            for (int r = 0; r < 4; r++) acc[mt][nt][r] = 0.f;

    const int KT = K / 32;
    LOAD_TILE(0, 0);

    for (int kt = 0; kt < KT; kt++) {
        const int buf = kt & 1;
        if (kt + 1 < KT) {
            LOAD_TILE(kt + 1, (kt + 1) & 1);
            CP_WAIT(1);
        } else {
            CP_WAIT(0);
        }
        __syncthreads();

        const uint32_t sA = sbase + buf * (BUF_FLOATS * 4);
        const uint32_t sB = sA + A_FLOATS * 4;

#pragma unroll
        for (int s = 0; s < 4; s++) {
            const int kb = s * 8;
            uint32_t af[4][4], bf[4][2];
#pragma unroll
            for (int mt = 0; mt < 4; mt++)
                LDSM_X4(af[mt][0], af[mt][1], af[mt][2], af[mt][3],
                        sA + (uint32_t)((a_row + mt * 16) * ASTRIDE + kb + a_col) * 4);
            LDSM_X4(bf[0][0], bf[0][1], bf[1][0], bf[1][1],
                    sB + (uint32_t)(b_row * ASTRIDE + kb + b_col) * 4);
            LDSM_X4(bf[2][0], bf[2][1], bf[3][0], bf[3][1],
                    sB + (uint32_t)((b_row + 16) * ASTRIDE + kb + b_col) * 4);
#pragma unroll
            for (int mt = 0; mt < 4; mt++)
#pragma unroll
                for (int nt = 0; nt < 4; nt++)
                    MMA_TF32(acc[mt][nt], af[mt][0], af[mt][1], af[mt][2], af[mt][3],
                             bf[nt][0], bf[nt][1]);
        }
        __syncthreads();
    }

    // epilogue
#pragma unroll
    for (int mt = 0; mt < 4; mt++) {
#pragma unroll
        for (int nt = 0; nt < 4; nt++) {
            const int r0 = m0 + warp_m * 64 + mt * 16 + fr;
            const int nloc = warp_n * 32 + nt * 8 + fc * 2;
            float2 v0 = make_float2(acc[mt][nt][0], acc[mt][nt][1]);
            float2 v1 = make_float2(acc[mt][nt][2], acc[mt][nt][3]);
            if (MODE == 1) {
                const int b0_ = r0 >> 11, l0 = r0 & 2047;
                const int b1_ = (r0 + 8) >> 11, l1 = (r0 + 8) & 2047;
                if (mid == 2) {
                    // transposed V: [b][h][d][l], tf32 bits
                    const size_t vb0 = ((size_t)(b0_ * HH + bxm) * DH + nloc) * LL;
                    const size_t vb1 = ((size_t)(b1_ * HH + bxm) * DH + nloc) * LL;
                    Cv[vb0 + l0]      = f2tf32(v0.x);
                    Cv[vb0 + LL + l0] = f2tf32(v0.y);
                    Cv[vb1 + l1]      = f2tf32(v1.x);
                    Cv[vb1 + LL + l1] = f2tf32(v1.y);
                } else {
                    float* Ct = (mid == 0) ? Cq : Ck;
                    const size_t o0 = (((size_t)(b0_ * HH + bxm)) * LL + l0) * DH + nloc;
                    const size_t o1 = (((size_t)(b1_ * HH + bxm)) * LL + l1) * DH + nloc;
                    *(float2*)(Ct + o0) = v0;
                    *(float2*)(Ct + o1) = v1;
                }
            } else {
                *(float2*)(Cout + (size_t)r0 * N + n0 + nloc) = v0;
                *(float2*)(Cout + (size_t)(r0 + 8) * N + n0 + nloc) = v1;
            }
        }
    }
#undef LOAD_TILE
}

// ---------------- RoPE + L2-normalize; writes tf32 bits in place ----------------
__global__ __launch_bounds__(256)
void rope_norm_kernel(float* __restrict__ t)
{
    const int gw = (blockIdx.x * 256 + threadIdx.x) >> 5;
    const int lane = threadIdx.x & 31;
    const int pos = gw & (LL - 1);
    float* row = t + (size_t)gw * DH;

    const float invf0 = g_invf[lane];
    const float invf1 = g_invf[lane + 32];
    const float pf = (float)pos;
    float s0, c0, s1, c1;
    sincosf(pf * invf0, &s0, &c0);
    sincosf(pf * invf1, &s1, &c1);

    float2 x = ((const float2*)row)[lane];
    float2 y = ((const float2*)row)[lane + 32];
    const float r0 = x.x * c0 - x.y * s0;
    const float r1 = x.y * c0 + x.x * s0;
    const float r2 = y.x * c1 - y.y * s1;
    const float r3 = y.y * c1 + y.x * s1;

    float ss = r0 * r0 + r1 * r1 + r2 * r2 + r3 * r3;
#pragma unroll
    for (int off = 16; off > 0; off >>= 1)
        ss += __shfl_xor_sync(0xffffffffu, ss, off);
    const float inv = 1.0f / (sqrtf(ss) + 1e-6f);

    uint32_t* rowu = (uint32_t*)row;
    ((uint2*)rowu)[lane]      = make_uint2(f2tf32(r0 * inv), f2tf32(r1 * inv));
    ((uint2*)rowu)[lane + 32] = make_uint2(f2tf32(r2 * inv), f2tf32(r3 * inv));
}

// ============================================================================
// tensor-core causal flash attention on tf32 bits, ldmatrix feeds
// k_s: K[kpos][d] stride 132 (also Q staging); v_s: Vt[d][kpos] stride 68;
// p_s: P[q][kpos] stride 68.
// ============================================================================
#define AKS 132
#define AVS 68
#define APS 68
#define AV_OFF (64 * AKS)                  // 8448
#define AP_OFF (AV_OFF + 128 * AVS)        // 17152
#define ATTN2_U32 (AP_OFF + 64 * APS)      // 21504
#define ATTN2_BYTES (ATTN2_U32 * 4)        // 86016

__global__ __launch_bounds__(128, 2)
void attn_mma_kernel(const float* __restrict__ scale_ptr)
{
    extern __shared__ __align__(16) uint32_t smu[];
    uint32_t* k_u = smu;
    uint32_t* v_u = smu + AV_OFF;
    uint32_t* p_u = smu + AP_OFF;

    const int qt = (int)gridDim.x - 1 - (int)blockIdx.x;   // heavy tiles first
    const int h = blockIdx.y, b = blockIdx.z;
    const int tid = threadIdx.x;
    const int wid = tid >> 5, lane = tid & 31;
    const int fr = lane >> 2, fc = lane & 3;
    const int t3 = lane >> 3, rr = lane & 7;
    const float sc2 = (*scale_ptr) * 1.4426950408889634f;

    const size_t head_off = (size_t)(b * HH + h) * LL * DH;
    const uint32_t* qptr = (const uint32_t*)g_q + head_off;
    const uint32_t* kptr = (const uint32_t*)g_k + head_off;
    const uint32_t* vtptr = g_v + head_off;          // [d][l] layout
    const int q0 = qt * 64;

    const uint32_t sK = smem_u32(smu);
    const uint32_t sV = sK + AV_OFF * 4;
    const uint32_t sP = sK + AP_OFF * 4;

    const int lr = tid >> 1, lh = tid & 1;           // K/Q loader slot
    const int vrow = tid >> 1, vhalf = tid & 1;      // V loader slot

    // ---- stage Q bits into k_s, preload A-frags via ldmatrix ----
    {
        const uint32_t* src = qptr + (size_t)(q0 + lr) * DH + lh * 64;
        uint32_t* dst = k_u + lr * AKS + lh * 64;
#pragma unroll
        for (int j = 0; j < 16; j++)
            *(uint4*)(dst + j * 4) = *(const uint4*)(src + j * 4);
    }
    __syncthreads();
    uint32_t qa[16][4];
    {
        const uint32_t qbase = sK +
            (uint32_t)((wid * 16 + (t3 & 1) * 8 + rr) * AKS + (t3 >> 1) * 4) * 4;
#pragma unroll
        for (int s = 0; s < 16; s++)
            LDSM_X4(qa[s][0], qa[s][1], qa[s][2], qa[s][3], qbase + (uint32_t)(s * 8) * 4);
    }

    float oacc[16][4];
#pragma unroll
    for (int nf = 0; nf < 16; nf++)
#pragma unroll
        for (int r = 0; r < 4; r++) oacc[nf][r] = 0.f;
    float m_[2] = {-1e30f, -1e30f};
    float l_[2] = {0.f, 0.f};

    const int row0 = q0 + wid * 16 + fr;

    // ldmatrix per-thread bases (row/col offsets inside tiles)
    const int kb_row = (t3 >> 1) * 8 + rr;   // + 16*jj  (K B-frags)
    const int kb_col = (t3 & 1) * 4;         // + 8*s
    const int vb_row = (t3 >> 1) * 8 + rr;   // + 16*nfp (V B-frags)
    const int vb_col = (t3 & 1) * 4;         // + 8*s2
    const int pa_row = wid * 16 + (t3 & 1) * 8 + rr;
    const int pa_col = (t3 >> 1) * 4;        // + 8*s2

    for (int kt = 0; kt <= qt; kt++) {
        const int k0 = kt * 64;
        __syncthreads();
        {
            // K: [kpos][d] rows, coalesced
            const uint32_t* ksrc = kptr + (size_t)(k0 + lr) * DH + lh * 64;
            uint32_t* kdst = k_u + lr * AKS + lh * 64;
#pragma unroll
            for (int j = 0; j < 16; j++)
                *(uint4*)(kdst + j * 4) = *(const uint4*)(ksrc + j * 4);
            // V: gmem [d][l] rows -> smem [d][kpos] rows
#pragma unroll
            for (int rp = 0; rp < 2; rp++) {
                const int d = vrow + rp * 64;
                const uint32_t* vsrc = vtptr + (size_t)d * LL + k0 + vhalf * 32;
                uint32_t* vdst = v_u + d * AVS + vhalf * 32;
#pragma unroll
                for (int j = 0; j < 8; j++)
                    *(uint4*)(vdst + j * 4) = *(const uint4*)(vsrc + j * 4);
            }
        }
        __syncthreads();

        // ---- S = Q K^T ----
        float sacc[8][4];
#pragma unroll
        for (int j = 0; j < 8; j++)
#pragma unroll
            for (int r = 0; r < 4; r++) sacc[j][r] = 0.f;

#pragma unroll
        for (int s = 0; s < 16; s++) {
#pragma unroll
            for (int jj = 0; jj < 4; jj++) {
                uint32_t b0a, b1a, b0b, b1b;
                LDSM_X4(b0a, b1a, b0b, b1b,
                        sK + (uint32_t)((jj * 16 + kb_row) * AKS + s * 8 + kb_col) * 4);
                MMA_TF32(sacc[2 * jj],     qa[s][0], qa[s][1], qa[s][2], qa[s][3], b0a, b1a);
                MMA_TF32(sacc[2 * jj + 1], qa[s][0], qa[s][1], qa[s][2], qa[s][3], b0b, b1b);
            }
        }

        // ---- mask (diagonal tile only) ----
        if (kt == qt) {
#pragma unroll
            for (int j = 0; j < 8; j++) {
                const int c0 = k0 + 8 * j + 2 * fc;
                if (c0 > row0)     sacc[j][0] = -1e30f;
                if (c0 + 1 > row0) sacc[j][1] = -1e30f;
                if (c0 > row0 + 8)     sacc[j][2] = -1e30f;
                if (c0 + 1 > row0 + 8) sacc[j][3] = -1e30f;
            }
        }

        // ---- online softmax ----
#pragma unroll
        for (int r2 = 0; r2 < 2; r2++) {
            float rmax = -1e30f;
#pragma unroll
            for (int j = 0; j < 8; j++)
                rmax = fmaxf(rmax, fmaxf(sacc[j][2 * r2], sacc[j][2 * r2 + 1]));
            rmax = fmaxf(rmax, __shfl_xor_sync(0xffffffffu, rmax, 1));
            rmax = fmaxf(rmax, __shfl_xor_sync(0xffffffffu, rmax, 2));
            const float mn = fmaxf(m_[r2], rmax);
            const float fs = fast_exp2(sc2 * (m_[r2] - mn));
            const float base = sc2 * mn;
            float rs = 0.f;
            uint32_t* prow = p_u + (wid * 16 + fr + 8 * r2) * APS + 2 * fc;
#pragma unroll
            for (int j = 0; j < 8; j++) {
                float p0 = fast_exp2(__fmaf_rn(sc2, sacc[j][2 * r2], -base));
                float p1 = fast_exp2(__fmaf_rn(sc2, sacc[j][2 * r2 + 1], -base));
                rs += p0 + p1;
                prow[8 * j]     = f2tf32(p0);
                prow[8 * j + 1] = f2tf32(p1);
            }
            rs += __shfl_xor_sync(0xffffffffu, rs, 1);
            rs += __shfl_xor_sync(0xffffffffu, rs, 2);
            l_[r2] = l_[r2] * fs + rs;
            m_[r2] = mn;
#pragma unroll
            for (int nf = 0; nf < 16; nf++) {
                oacc[nf][2 * r2]     *= fs;
                oacc[nf][2 * r2 + 1] *= fs;
            }
        }
        __syncwarp();

        // ---- O += P V ----
#pragma unroll
        for (int s2 = 0; s2 < 8; s2++) {
            uint32_t a0, a1, a2, a3;
            LDSM_X4(a0, a1, a2, a3,
                    sP + (uint32_t)(pa_row * APS + s2 * 8 + pa_col) * 4);
#pragma unroll
            for (int nfp = 0; nfp < 8; nfp++) {
                uint32_t b0a, b1a, b0b, b1b;
                LDSM_X4(b0a, b1a, b0b, b1b,
                        sV + (uint32_t)((nfp * 16 + vb_row) * AVS + s2 * 8 + vb_col) * 4);
                MMA_TF32(oacc[2 * nfp],     a0, a1, a2, a3, b0a, b1a);
                MMA_TF32(oacc[2 * nfp + 1], a0, a1, a2, a3, b0b, b1b);
            }
        }
        __syncwarp();
    }

    // ---- epilogue: normalize + write tf32 bits [b][l][h*128+d] ----
    const float inv0 = 1.f / l_[0];
    const float inv1 = 1.f / l_[1];
    uint32_t* d0p = g_attn + ((size_t)(b * LL + row0)) * DD + h * DH + 2 * fc;
    uint32_t* d1p = g_attn + ((size_t)(b * LL + row0 + 8)) * DD + h * DH + 2 * fc;
#pragma unroll
    for (int nf = 0; nf < 16; nf++) {
        *(uint2*)(d0p + 8 * nf) = make_uint2(f2tf32(oacc[nf][0] * inv0),
                                             f2tf32(oacc[nf][1] * inv0));
        *(uint2*)(d1p + 8 * nf) = make_uint2(f2tf32(oacc[nf][2] * inv1),
                                             f2tf32(oacc[nf][3] * inv1));
    }
}

// ---------------- launch ----------------
extern "C" void kernel_launch(void* const* d_in, const int* in_sizes, int n_in,
                              void* d_out, int out_size)
{
    const float* x     = (const float*)d_in[0];
    const float* Wq    = (const float*)d_in[1];
    const float* Wk    = (const float*)d_in[2];
    const float* Wv    = (const float*)d_in[3];
    const float* Wout  = (const float*)d_in[4];
    const float* scale = (const float*)d_in[5];
    float* out = (float*)d_out;

    float *qp, *kp;
    uint32_t *vp, *ap, *xc, *wqc, *wkc, *wvc, *woc;
    cudaGetSymbolAddress((void**)&qp,  g_q);
    cudaGetSymbolAddress((void**)&kp,  g_k);
    cudaGetSymbolAddress((void**)&vp,  g_v);
    cudaGetSymbolAddress((void**)&ap,  g_attn);
    cudaGetSymbolAddress((void**)&xc,  g_xc);
    cudaGetSymbolAddress((void**)&wqc, g_wqc);
    cudaGetSymbolAddress((void**)&wkc, g_wkc);
    cudaGetSymbolAddress((void**)&wvc, g_wvc);
    cudaGetSymbolAddress((void**)&woc, g_woc);

    build_invf_kernel<<<1, 64>>>();

    const int M = BB * LL;           // 4096
    const int XN4 = (M * DD) / 4;
    cvt_kernel<<<XN4 / 256, 256>>>(x, xc, XN4);
    dim3 tgrid(DD / 32, DD / 32);
    cvt_t_kernel<<<tgrid, 256>>>(Wq, wqc);
    cvt_t_kernel<<<tgrid, 256>>>(Wk, wkc);
    cvt_t_kernel<<<tgrid, 256>>>(Wv, wvc);
    cvt_t_kernel<<<tgrid, 256>>>(Wout, woc);

    cudaFuncSetAttribute(mma_gemm_kernel<0>, cudaFuncAttributeMaxDynamicSharedMemorySize,
                         GEMM_SMEM_BYTES);
    cudaFuncSetAttribute(mma_gemm_kernel<1>, cudaFuncAttributeMaxDynamicSharedMemorySize,
                         GEMM_SMEM_BYTES);
    cudaFuncSetAttribute(attn_mma_kernel, cudaFuncAttributeMaxDynamicSharedMemorySize,
                         ATTN2_BYTES);

    // fused QKV: grid.x = 48 (16 n-blocks x 3 matrices)
    mma_gemm_kernel<1><<<dim3(48, M / 128), 256, GEMM_SMEM_BYTES>>>(
        xc, wqc, wkc, wvc, qp, kp, vp, nullptr, M, DD, DD);

    const int rope_blocks = (BB * HH * LL) / 8;
    rope_norm_kernel<<<rope_blocks, 256>>>(qp);
    rope_norm_kernel<<<rope_blocks, 256>>>(kp);

    attn_mma_kernel<<<dim3(LL / 64, HH, BB), 128, ATTN2_BYTES>>>(scale);

    mma_gemm_kernel<0><<<dim3(16, M / 128), 256, GEMM_SMEM_BYTES>>>(
        ap, woc, nullptr, nullptr, nullptr, nullptr, nullptr, out, M, DD, DD);
}